// round 8
// baseline (speedup 1.0000x reference)
#include <cuda_runtime.h>
#include <cstdint>

#define B_    4
#define KL    128
#define XL    4096
#define DIM   256
#define H_    8
#define HD    32
#define PB    8
#define NDIS  66
#define TDIM  768           // 3*DIM
#define SCALE 0.17677669529663687f
#define NMASK (B_ * H_ * XL * KL)
#define NSPLIT 32           // x-splits for k2/k3

// ---------------- scratch (device globals) ----------------
__device__ float    g_QKVx[B_ * XL * TDIM];
__device__ float    g_QKVk[B_ * KL * TDIM];
__device__ unsigned short g_pack[(size_t)NMASK];       // (b,h,k,x): rd | polar<<7 | mask<<10
__device__ float    g_oriP[NSPLIT * B_ * H_ * KL * PB];
__device__ int      g_mo[B_ * H_ * KL];
__device__ float    g_part[(size_t)B_ * H_ * NSPLIT * KL * 33];  // (l, acc[32])
__device__ float    g_preK[B_ * KL * DIM];
__device__ float    g_preX[B_ * XL * DIM];
__device__ unsigned g_flags;

// ---------------- mask dtype probe ----------------
__global__ void det_reset() { if (threadIdx.x == 0) g_flags = 0u; }

__global__ void det_scan(const unsigned* __restrict__ w)
{
    int i = blockIdx.x * blockDim.x + threadIdx.x;
    unsigned v = w[i];
    unsigned f = 0;
    if (v == 0x3F800000u) f |= 1u;
    else if (v != 0u && v != 1u) f |= 2u;
    for (int o = 16; o > 0; o >>= 1) f |= __shfl_xor_sync(0xffffffffu, f, o);
    if ((threadIdx.x & 31) == 0 && f) atomicOr(&g_flags, f);
}

// ---------------- pack16: rd+polar+mask(transposed) -> u16 (b,h,k,x) ------
__global__ void pack16(const void* __restrict__ mask,
                       const int* __restrict__ rd, const int* __restrict__ polar)
{
    __shared__ unsigned short rp_sh[32][66];
    __shared__ uint8_t m_sh[64][36];
    unsigned flags = g_flags;
    int mode = (flags & 1u) ? 2 : ((flags & 2u) ? 0 : 1);
    int x0 = blockIdx.x * 64, k0 = blockIdx.y * 32, b = blockIdx.z;
    int tx = threadIdx.x, ty = threadIdx.y;

#pragma unroll
    for (int ki = ty; ki < 32; ki += 8) {
        size_t rowb = ((size_t)(b * KL + k0 + ki)) * XL + x0;
#pragma unroll
        for (int xx = tx; xx < 64; xx += 32) {
            int r = rd[rowb + xx];
            int p = polar[rowb + xx];
            rp_sh[ki][xx] = (unsigned short)(r | (p << 7));
        }
    }
    for (int h = 0; h < H_; h++) {
        size_t mb = ((size_t)((b * H_ + h)) * XL + x0) * KL + k0;
#pragma unroll
        for (int xi = ty; xi < 64; xi += 8) {
            uint8_t v;
            if (mode == 1)      v = ((const int*)mask)[mb + (size_t)xi * KL + tx] != 0;
            else if (mode == 2) v = ((const float*)mask)[mb + (size_t)xi * KL + tx] != 0.f;
            else                v = ((const uint8_t*)mask)[mb + (size_t)xi * KL + tx] != 0;
            m_sh[xi][tx] = v;
        }
        __syncthreads();
        size_t ob = ((size_t)((b * H_ + h) * KL + k0)) * XL + x0;
#pragma unroll
        for (int ki = ty; ki < 32; ki += 8)
#pragma unroll
            for (int xx = tx; xx < 64; xx += 32)
                g_pack[ob + (size_t)ki * XL + xx] =
                    (unsigned short)(rp_sh[ki][xx] | ((unsigned short)m_sh[xx][ki] << 10));
        __syncthreads();
    }
}

// ---------------- 3xTF32 tensor-core GEMM, pre-split staging --------------
__device__ __forceinline__ void split_tf32(float x, uint32_t& hi, uint32_t& lo)
{
    asm("cvt.rna.tf32.f32 %0, %1;" : "=r"(hi) : "f"(x));
    float r = x - __uint_as_float(hi);
    asm("cvt.rna.tf32.f32 %0, %1;" : "=r"(lo) : "f"(r));
}

__device__ __forceinline__ void mma_tf32(float* c, const uint32_t* a, uint32_t b0, uint32_t b1)
{
    asm("mma.sync.aligned.m16n8k8.row.col.f32.tf32.tf32.f32 "
        "{%0,%1,%2,%3}, {%4,%5,%6,%7}, {%8,%9}, {%0,%1,%2,%3};"
        : "+f"(c[0]), "+f"(c[1]), "+f"(c[2]), "+f"(c[3])
        : "r"(a[0]), "r"(a[1]), "r"(a[2]), "r"(a[3]), "r"(b0), "r"(b1));
}

__global__ __launch_bounds__(256, 2) void gemm_tf32(
    const float* __restrict__ A, const float* __restrict__ Bm,
    const float* __restrict__ bias, float* __restrict__ C,
    int M, int N, int K)
{
    __shared__ uint32_t AsH[128][20];
    __shared__ uint32_t AsL[128][20];
    __shared__ uint32_t BsH[16][132];
    __shared__ uint32_t BsL[16][132];
    int tid = threadIdx.x;
    int wid = tid >> 5, lane = tid & 31;
    int quad = lane >> 2, qt = lane & 3;
    int wm = wid & 1, wn = wid >> 1;
    int cCol = blockIdx.x, cRow = blockIdx.y;
    const float* Ap = A + (size_t)cRow * 128 * K;
    const float* Bp = Bm + cCol * 128;

    float acc[4][4][4];
#pragma unroll
    for (int i = 0; i < 4; i++)
#pragma unroll
        for (int j = 0; j < 4; j++)
#pragma unroll
            for (int c = 0; c < 4; c++) acc[i][j][c] = 0.f;

    for (int k0 = 0; k0 < K; k0 += 16) {
        // stage + split A tile (128x16), one float per thread x8
#pragma unroll
        for (int j = 0; j < 8; j++) {
            int f = tid + 256 * j;
            int r = f >> 4, c = f & 15;
            uint32_t h, l;
            split_tf32(Ap[(size_t)r * K + k0 + c], h, l);
            AsH[r][c] = h;
            AsL[r][c] = l;
        }
        // stage + split B tile (16x128)
#pragma unroll
        for (int j = 0; j < 8; j++) {
            int f = tid + 256 * j;
            int r = f >> 7, c = f & 127;
            uint32_t h, l;
            split_tf32(Bp[(size_t)(k0 + r) * N + c], h, l);
            BsH[r][c] = h;
            BsL[r][c] = l;
        }
        __syncthreads();

#pragma unroll
        for (int kk = 0; kk < 2; kk++) {
            uint32_t ahi[4][4], alo[4][4];
#pragma unroll
            for (int mi = 0; mi < 4; mi++) {
                int ar = wm * 64 + mi * 16 + quad;
                int ac = kk * 8 + qt;
                ahi[mi][0] = AsH[ar][ac];         alo[mi][0] = AsL[ar][ac];
                ahi[mi][1] = AsH[ar + 8][ac];     alo[mi][1] = AsL[ar + 8][ac];
                ahi[mi][2] = AsH[ar][ac + 4];     alo[mi][2] = AsL[ar][ac + 4];
                ahi[mi][3] = AsH[ar + 8][ac + 4]; alo[mi][3] = AsL[ar + 8][ac + 4];
            }
#pragma unroll
            for (int ni = 0; ni < 4; ni++) {
                int bc = wn * 32 + ni * 8 + quad;
                int br = kk * 8 + qt;
                uint32_t bh0 = BsH[br][bc], bh1 = BsH[br + 4][bc];
                uint32_t bl0 = BsL[br][bc], bl1 = BsL[br + 4][bc];
#pragma unroll
                for (int mi = 0; mi < 4; mi++) {
                    mma_tf32(acc[mi][ni], ahi[mi], bh0, bh1);
                    mma_tf32(acc[mi][ni], alo[mi], bh0, bh1);
                    mma_tf32(acc[mi][ni], ahi[mi], bl0, bl1);
                }
            }
        }
        __syncthreads();
    }

#pragma unroll
    for (int mi = 0; mi < 4; mi++) {
#pragma unroll
        for (int ni = 0; ni < 4; ni++) {
            int r0 = cRow * 128 + wm * 64 + mi * 16 + quad;
            int c0 = cCol * 128 + wn * 32 + ni * 8 + 2 * qt;
            float b0 = bias ? bias[c0] : 0.f;
            float b1 = bias ? bias[c0 + 1] : 0.f;
            float2 v01 = make_float2(acc[mi][ni][0] + b0, acc[mi][ni][1] + b1);
            float2 v23 = make_float2(acc[mi][ni][2] + b0, acc[mi][ni][3] + b1);
            *(float2*)&C[(size_t)r0 * N + c0] = v01;
            *(float2*)&C[(size_t)(r0 + 8) * N + c0] = v23;
        }
    }
}

// ---------------- K2: orientation bins ----------------
// grid (NSPLIT, H, B), block 128 (thread = k); 128 x per block
__global__ __launch_bounds__(128) void k2_scores()
{
    int k = threadIdx.x;
    int xc = blockIdx.x, h = blockIdx.y, b = blockIdx.z;
    int bh = b * H_ + h;
    int xbase = xc * (XL / NSPLIT);
    __shared__ float kx_sh[64 * 32];
    __shared__ unsigned pk_sh[128 * 33];

    float4 kq4[8];
    const float4* kqp = (const float4*)&g_QKVk[((size_t)(b * KL + k)) * TDIM + h * HD];
#pragma unroll
    for (int i = 0; i < 8; i++) kq4[i] = kqp[i];

    float bins[8];
#pragma unroll
    for (int o = 0; o < 8; o++) bins[o] = 0.f;

    const unsigned* pkg = (const unsigned*)&g_pack[(size_t)bh * KL * XL];

    for (int c = 0; c < 2; c++) {
        int xs = xbase + c * 64;
        __syncthreads();
        for (int g = threadIdx.x; g < 512; g += 128) {
            int row = g >> 3, c4 = g & 7;
            ((float4*)kx_sh)[g] =
                *(const float4*)&g_QKVx[((size_t)(b * XL + xs + row)) * TDIM + DIM + h * HD + c4 * 4];
        }
        for (int g = threadIdx.x; g < 128 * 32; g += 128) {
            int row = g >> 5, col = g & 31;
            pk_sh[row * 33 + col] = pkg[(size_t)row * (XL / 2) + (xs >> 1) + col];
        }
        __syncthreads();
        const unsigned short* prow = (const unsigned short*)&pk_sh[k * 33];
        for (int j0 = 0; j0 < 64; j0 += 4) {
#pragma unroll
            for (int jj = 0; jj < 4; jj++) {
                const float4* kx4 = (const float4*)&kx_sh[(j0 + jj) * 32];
                float a = 0.f;
#pragma unroll
                for (int d = 0; d < 8; d++) {
                    float4 v = kx4[d];
                    a += v.x * kq4[d].x + v.y * kq4[d].y + v.z * kq4[d].z + v.w * kq4[d].w;
                }
                float as = fabsf(a * SCALE);
                int pv = (prow[j0 + jj] >> 7) & 7;
#pragma unroll
                for (int o = 0; o < 8; o++) bins[o] += (pv == o) ? as : 0.f;
            }
        }
    }
    float* orow = &g_oriP[((size_t)xc * B_ * H_ * KL + bh * KL + k) * 8];
#pragma unroll
    for (int o = 0; o < 8; o++) orow[o] = bins[o];
}

// ---------------- K2c: reduce slices + argmax ----------------
__global__ void k2_argmax()
{
    int idx = blockIdx.x * blockDim.x + threadIdx.x;
    if (idx >= B_ * H_ * KL) return;
    float s[8];
#pragma unroll
    for (int o = 0; o < 8; o++) s[o] = 0.f;
    for (int xc = 0; xc < NSPLIT; xc++) {
        const float* p = &g_oriP[((size_t)xc * B_ * H_ * KL + idx) * 8];
#pragma unroll
        for (int o = 0; o < 8; o++) s[o] += p[o];
    }
    int best = 0;
    float bv = s[0];
#pragma unroll
    for (int p = 1; p < 8; p++)
        if (s[p] > bv) { bv = s[p]; best = p; }
    g_mo[idx] = best;
}

// ---------------- K3: kernel->x attention (no-max softmax, 32 splits) -----
// grid (NSPLIT, H, B), block 128 (thread = k)
__global__ __launch_bounds__(128) void k3_kattn(
    const float* __restrict__ dis_embed, const float* __restrict__ polar_emb)
{
    int k = threadIdx.x;
    int xs = blockIdx.x, h = blockIdx.y, b = blockIdx.z;
    int bh = b * H_ + h;
    __shared__ float kx_sh[64 * 32];
    __shared__ float V_sh[64 * 32];
    __shared__ unsigned pk_sh[128 * 33];
    __shared__ float de_sh[NDIS];
    __shared__ float pe_sh[8];
    if (k < NDIS) de_sh[k] = dis_embed[k * H_ + h];
    if (k < 8) pe_sh[k] = polar_emb[k];
    int mo = g_mo[bh * KL + k];

    float4 kq4[8];
    const float4* kqp = (const float4*)&g_QKVk[((size_t)(b * KL + k)) * TDIM + h * HD];
#pragma unroll
    for (int i = 0; i < 8; i++) kq4[i] = kqp[i];

    const unsigned* pkg = (const unsigned*)&g_pack[(size_t)bh * KL * XL];

    float l = 0.f;
    float acc[32];
#pragma unroll
    for (int d = 0; d < 32; d++) acc[d] = 0.f;

    int xbase = xs * (XL / NSPLIT);
    for (int c = 0; c < 2; c++) {
        int x0 = xbase + c * 64;
        __syncthreads();
        for (int g = threadIdx.x; g < 512; g += 128) {
            int row = g >> 3, c4 = g & 7;
            size_t rb = ((size_t)(b * XL + x0 + row)) * TDIM + h * HD + c4 * 4;
            ((float4*)kx_sh)[g] = *(const float4*)&g_QKVx[rb + DIM];
            ((float4*)V_sh)[g]  = *(const float4*)&g_QKVx[rb + 2 * DIM];
        }
        for (int g = threadIdx.x; g < 128 * 32; g += 128) {
            int row = g >> 5, col = g & 31;
            pk_sh[row * 33 + col] = pkg[(size_t)row * (XL / 2) + (x0 >> 1) + col];
        }
        __syncthreads();
        const unsigned short* prow = (const unsigned short*)&pk_sh[k * 33];
        for (int j0 = 0; j0 < 64; j0 += 4) {
#pragma unroll
            for (int jj = 0; jj < 4; jj++) {
                int j = j0 + jj;
                const float4* kx4 = (const float4*)&kx_sh[j * 32];
                float a = 0.f;
#pragma unroll
                for (int d = 0; d < 8; d++) {
                    float4 v = kx4[d];
                    a += v.x * kq4[d].x + v.y * kq4[d].y + v.z * kq4[d].z + v.w * kq4[d].w;
                }
                unsigned short p = prow[j];
                float t = a * SCALE + de_sh[p & 127] + pe_sh[(((p >> 7) & 7) - mo) & 7];
                float w = (p >> 10) ? 0.f : __expf(t);
                l += w;
                const float4* vp = (const float4*)&V_sh[j * 32];
#pragma unroll
                for (int d = 0; d < 8; d++) {
                    float4 v = vp[d];
                    acc[d * 4 + 0] += w * v.x;
                    acc[d * 4 + 1] += w * v.y;
                    acc[d * 4 + 2] += w * v.z;
                    acc[d * 4 + 3] += w * v.w;
                }
            }
        }
    }
    float* pp = &g_part[(((size_t)bh * NSPLIT + xs) * KL + k) * 33];
    pp[0] = l;
#pragma unroll
    for (int d = 0; d < 32; d++) pp[1 + d] = acc[d];
}

// ---------------- K3c: combine x-splits -> preK ----------------
__global__ void k3_combine()
{
    int idx = blockIdx.x * blockDim.x + threadIdx.x;
    if (idx >= B_ * H_ * KL * 32) return;
    int d = idx & 31;
    int k = (idx >> 5) & (KL - 1);
    int bh = idx >> 12;
    int h = bh % H_, b = bh / H_;
    const float* base = &g_part[((size_t)bh * NSPLIT) * KL * 33 + (size_t)k * 33];
    float L = 0.f, A = 0.f;
    const size_t SSTR = (size_t)KL * 33;
#pragma unroll 8
    for (int s = 0; s < NSPLIT; s++) {
        L += base[s * SSTR];
        A += base[s * SSTR + 1 + d];
    }
    g_preK[((size_t)b * KL + k) * DIM + h * HD + d] = A / L;
}

// ---------------- K4: x->kernel attention (no-max softmax) ----------------
// grid (XL/128, H, B), block 128 (thread = x)
__global__ __launch_bounds__(128) void k4_xattn(
    const float* __restrict__ dis_embed, const float* __restrict__ polar_emb)
{
    __shared__ float kk_sh[KL * HD];
    __shared__ float kv_sh[KL * HD];
    __shared__ float de_sh[NDIS];
    __shared__ float pe_sh[8];
    __shared__ int   mo_sh[KL];
    int tid = threadIdx.x;
    int xc = blockIdx.x, h = blockIdx.y, b = blockIdx.z;
    int bh = b * H_ + h;

    for (int g = tid; g < KL * HD / 4; g += 128) {
        int row = g >> 3, c4 = g & 7;
        ((float4*)kk_sh)[g] =
            *(const float4*)&g_QKVk[((size_t)(b * KL + row)) * TDIM + DIM + h * HD + c4 * 4];
        ((float4*)kv_sh)[g] =
            *(const float4*)&g_QKVk[((size_t)(b * KL + row)) * TDIM + 2 * DIM + h * HD + c4 * 4];
    }
    if (tid < NDIS) de_sh[tid] = dis_embed[tid * H_ + h];
    if (tid < 8) pe_sh[tid] = polar_emb[tid];
    if (tid < KL) mo_sh[tid] = g_mo[bh * KL + tid];
    __syncthreads();

    int x = xc * 128 + tid;
    float4 q4[8];
    const float4* qp = (const float4*)&g_QKVx[((size_t)(b * XL + x)) * TDIM + h * HD];
#pragma unroll
    for (int i = 0; i < 8; i++) q4[i] = qp[i];
    const unsigned short* pk = &g_pack[(size_t)bh * KL * XL + x];

    float l = 0.f;
    float acc[32];
#pragma unroll
    for (int d = 0; d < 32; d++) acc[d] = 0.f;

    for (int k0 = 0; k0 < KL; k0 += 4) {
#pragma unroll
        for (int ki = 0; ki < 4; ki++) {
            int kidx = k0 + ki;
            const float4* kkp = (const float4*)&kk_sh[kidx * HD];
            float s = 0.f;
#pragma unroll
            for (int d = 0; d < 8; d++) {
                float4 a = kkp[d];
                s += a.x * q4[d].x + a.y * q4[d].y + a.z * q4[d].z + a.w * q4[d].w;
            }
            unsigned short p = pk[(size_t)kidx * XL];
            float t = s * SCALE + de_sh[p & 127] + pe_sh[(((p >> 7) & 7) - mo_sh[kidx]) & 7];
            float w = (p >> 10) ? 0.f : __expf(t);
            l += w;
            const float4* vp = (const float4*)&kv_sh[kidx * HD];
#pragma unroll
            for (int d = 0; d < 8; d++) {
                float4 v = vp[d];
                acc[d * 4 + 0] += w * v.x;
                acc[d * 4 + 1] += w * v.y;
                acc[d * 4 + 2] += w * v.z;
                acc[d * 4 + 3] += w * v.w;
            }
        }
    }
    float invl = 1.f / l;
    float* out = &g_preX[((size_t)(b * XL + x)) * DIM + h * HD];
#pragma unroll
    for (int d = 0; d < 8; d++) {
        float4 v;
        v.x = acc[d * 4 + 0] * invl;
        v.y = acc[d * 4 + 1] * invl;
        v.z = acc[d * 4 + 2] * invl;
        v.w = acc[d * 4 + 3] * invl;
        *(float4*)&out[d * 4] = v;
    }
}

// ---------------- host launcher ----------------
extern "C" void kernel_launch(void* const* d_in, const int* in_sizes, int n_in,
                              void* d_out, int out_size)
{
    const float* x     = (const float*)d_in[0];
    const float* kern  = (const float*)d_in[1];
    const int*   rd    = (const int*)d_in[2];
    const int*   polar = (const int*)d_in[3];
    const void*  mask  = d_in[4];
    const float* Wqkv  = (const float*)d_in[5];
    const float* dis   = (const float*)d_in[6];
    const float* pemb  = (const float*)d_in[7];
    const float* Wproj = (const float*)d_in[8];
    const float* bproj = (const float*)d_in[9];
    float* out = (float*)d_out;

    float* pQKVx; cudaGetSymbolAddress((void**)&pQKVx, g_QKVx);
    float* pQKVk; cudaGetSymbolAddress((void**)&pQKVk, g_QKVk);
    float* pPreX; cudaGetSymbolAddress((void**)&pPreX, g_preX);
    float* pPreK; cudaGetSymbolAddress((void**)&pPreK, g_preK);

    // mask dtype probe + packed bias table
    det_reset<<<1, 32>>>();
    det_scan<<<256, 256>>>((const unsigned*)mask);
    pack16<<<dim3(XL / 64, KL / 32, B_), dim3(32, 8)>>>(mask, rd, polar);

    // QKV projections (3xTF32 tensor cores, pre-split staging)
    gemm_tf32<<<dim3(TDIM / 128, (B_ * XL) / 128), 256>>>(x, Wqkv, nullptr, pQKVx, B_ * XL, TDIM, DIM);
    gemm_tf32<<<dim3(TDIM / 128, (B_ * KL) / 128), 256>>>(kern, Wqkv, nullptr, pQKVk, B_ * KL, TDIM, DIM);

    // orientation bins + argmax
    k2_scores<<<dim3(NSPLIT, H_, B_), 128>>>();
    k2_argmax<<<(B_ * H_ * KL + 255) / 256, 256>>>();

    // kernel->x attention
    k3_kattn<<<dim3(NSPLIT, H_, B_), 128>>>(dis, pemb);
    k3_combine<<<(B_ * H_ * KL * 32 + 255) / 256, 256>>>();

    // x->kernel attention
    k4_xattn<<<dim3(XL / 128, H_, B_), 128>>>(dis, pemb);

    // output projections
    gemm_tf32<<<dim3(DIM / 128, (B_ * XL) / 128), 256>>>(pPreX, Wproj, bproj, out, B_ * XL, DIM, DIM);
    gemm_tf32<<<dim3(DIM / 128, (B_ * KL) / 128), 256>>>(pPreK, Wproj, bproj, out + (size_t)B_ * XL * DIM, B_ * KL, DIM, DIM);
}

// round 9
// speedup vs baseline: 1.1536x; 1.1536x over previous
#include <cuda_runtime.h>
#include <cuda_bf16.h>
#include <cstdint>

#define B_    4
#define KL    128
#define XL    4096
#define DIM   256
#define H_    8
#define HD    32
#define PB    8
#define NDIS  66
#define TDIM  768           // 3*DIM
#define SCALE 0.17677669529663687f
#define NMASK (B_ * H_ * XL * KL)
#define NSPLIT 32           // x-splits for k2/k3

// ---------------- scratch (device globals) ----------------
__device__ float    g_QKVx[B_ * XL * TDIM];
__device__ float    g_QKVk[B_ * KL * TDIM];
__device__ unsigned short g_pack[(size_t)NMASK];       // (b,h,k,x): rd | polar<<7 | mask<<10
__device__ float    g_oriP[NSPLIT * B_ * H_ * KL * PB];
__device__ int      g_mo[B_ * H_ * KL];
__device__ float    g_part[(size_t)B_ * H_ * NSPLIT * KL * 33];  // (l, acc[32])
__device__ float    g_preK[B_ * KL * DIM];
__device__ float    g_preX[B_ * XL * DIM];
__device__ unsigned g_flags;

// ---------------- mask dtype probe ----------------
__global__ void det_reset() { if (threadIdx.x == 0) g_flags = 0u; }

__global__ void det_scan(const unsigned* __restrict__ w)
{
    int i = blockIdx.x * blockDim.x + threadIdx.x;
    unsigned v = w[i];
    unsigned f = 0;
    if (v == 0x3F800000u) f |= 1u;
    else if (v != 0u && v != 1u) f |= 2u;
    for (int o = 16; o > 0; o >>= 1) f |= __shfl_xor_sync(0xffffffffu, f, o);
    if ((threadIdx.x & 31) == 0 && f) atomicOr(&g_flags, f);
}

// ---------------- pack16: rd+polar+mask(transposed) -> u16 (b,h,k,x) ------
__global__ void pack16(const void* __restrict__ mask,
                       const int* __restrict__ rd, const int* __restrict__ polar)
{
    __shared__ unsigned short rp_sh[32][66];
    __shared__ uint8_t m_sh[64][36];
    unsigned flags = g_flags;
    int mode = (flags & 1u) ? 2 : ((flags & 2u) ? 0 : 1);
    int x0 = blockIdx.x * 64, k0 = blockIdx.y * 32, b = blockIdx.z;
    int tx = threadIdx.x, ty = threadIdx.y;

#pragma unroll
    for (int ki = ty; ki < 32; ki += 8) {
        size_t rowb = ((size_t)(b * KL + k0 + ki)) * XL + x0;
#pragma unroll
        for (int xx = tx; xx < 64; xx += 32) {
            int r = rd[rowb + xx];
            int p = polar[rowb + xx];
            rp_sh[ki][xx] = (unsigned short)(r | (p << 7));
        }
    }
    for (int h = 0; h < H_; h++) {
        size_t mb = ((size_t)((b * H_ + h)) * XL + x0) * KL + k0;
#pragma unroll
        for (int xi = ty; xi < 64; xi += 8) {
            uint8_t v;
            if (mode == 1)      v = ((const int*)mask)[mb + (size_t)xi * KL + tx] != 0;
            else if (mode == 2) v = ((const float*)mask)[mb + (size_t)xi * KL + tx] != 0.f;
            else                v = ((const uint8_t*)mask)[mb + (size_t)xi * KL + tx] != 0;
            m_sh[xi][tx] = v;
        }
        __syncthreads();
        size_t ob = ((size_t)((b * H_ + h) * KL + k0)) * XL + x0;
#pragma unroll
        for (int ki = ty; ki < 32; ki += 8)
#pragma unroll
            for (int xx = tx; xx < 64; xx += 32)
                g_pack[ob + (size_t)ki * XL + xx] =
                    (unsigned short)(rp_sh[ki][xx] | ((unsigned short)m_sh[xx][ki] << 10));
        __syncthreads();
    }
}

// ---------------- bf16x3 tensor-core GEMM (m16n8k16) ----------------------
// x = hi + lo (bf16 each); x*y ~= hi*hi + lo*hi + hi*lo  (drop lo*lo ~2^-16)
__device__ __forceinline__ uint32_t split_pack(float x0, float x1, uint32_t& lo_pack)
{
    __nv_bfloat16 h0 = __float2bfloat16(x0);
    __nv_bfloat16 h1 = __float2bfloat16(x1);
    float l0 = x0 - __bfloat162float(h0);
    float l1 = x1 - __bfloat162float(h1);
    __nv_bfloat162 hp = __halves2bfloat162(h0, h1);
    __nv_bfloat162 lp = __halves2bfloat162(__float2bfloat16(l0), __float2bfloat16(l1));
    lo_pack = *(uint32_t*)&lp;
    return *(uint32_t*)&hp;
}

__device__ __forceinline__ void mma_bf16(float* c, const uint32_t* a, uint32_t b0, uint32_t b1)
{
    asm("mma.sync.aligned.m16n8k16.row.col.f32.bf16.bf16.f32 "
        "{%0,%1,%2,%3}, {%4,%5,%6,%7}, {%8,%9}, {%0,%1,%2,%3};"
        : "+f"(c[0]), "+f"(c[1]), "+f"(c[2]), "+f"(c[3])
        : "r"(a[0]), "r"(a[1]), "r"(a[2]), "r"(a[3]), "r"(b0), "r"(b1));
}

// Block 128x128, BK=32, 256 threads (8 warps: 2(m) x 4(n), warp tile 64x32)
__global__ __launch_bounds__(256, 2) void gemm_bf16x3(
    const float* __restrict__ A, const float* __restrict__ Bm,
    const float* __restrict__ bias, float* __restrict__ C,
    int M, int N, int K)
{
    __shared__ uint32_t AsH[128][20];   // [row][k-pair], pad 20 -> conflict-free frags
    __shared__ uint32_t AsL[128][20];
    __shared__ uint32_t BsH[16][136];   // [k-pair][col], pad 136 -> conflict-free frags
    __shared__ uint32_t BsL[16][136];
    int tid = threadIdx.x;
    int wid = tid >> 5, lane = tid & 31;
    int g = lane >> 2, t = lane & 3;
    int wm = wid & 1, wn = wid >> 1;
    int cCol = blockIdx.x, cRow = blockIdx.y;
    const float* Ap = A + (size_t)cRow * 128 * K;
    const float* Bp = Bm + cCol * 128;

    float acc[4][4][4];
#pragma unroll
    for (int i = 0; i < 4; i++)
#pragma unroll
        for (int j = 0; j < 4; j++)
#pragma unroll
            for (int c = 0; c < 4; c++) acc[i][j][c] = 0.f;

    for (int k0 = 0; k0 < K; k0 += 32) {
        // A tile 128x32: 2048 k-pairs, 8 per thread (float2 loads, coalesced)
#pragma unroll
        for (int j = 0; j < 8; j++) {
            int f = tid + 256 * j;
            int r = f >> 4, p = f & 15;
            float2 v = *(const float2*)&Ap[(size_t)r * K + k0 + 2 * p];
            uint32_t lo, hi = split_pack(v.x, v.y, lo);
            AsH[r][p] = hi;
            AsL[r][p] = lo;
        }
        // B tile 32x128: 16 pair-rows x 128 cols, 8 per thread
#pragma unroll
        for (int j = 0; j < 8; j++) {
            int f = tid + 256 * j;
            int p = f >> 7, c = f & 127;
            float v0 = Bp[(size_t)(k0 + 2 * p) * N + c];
            float v1 = Bp[(size_t)(k0 + 2 * p + 1) * N + c];
            uint32_t lo, hi = split_pack(v0, v1, lo);
            BsH[p][c] = hi;
            BsL[p][c] = lo;
        }
        __syncthreads();

#pragma unroll
        for (int kk = 0; kk < 2; kk++) {
            uint32_t ah[4][4], al[4][4];
#pragma unroll
            for (int mi = 0; mi < 4; mi++) {
                int ar = wm * 64 + mi * 16 + g;
                int pc = kk * 8 + t;
                ah[mi][0] = AsH[ar][pc];         al[mi][0] = AsL[ar][pc];
                ah[mi][1] = AsH[ar + 8][pc];     al[mi][1] = AsL[ar + 8][pc];
                ah[mi][2] = AsH[ar][pc + 4];     al[mi][2] = AsL[ar][pc + 4];
                ah[mi][3] = AsH[ar + 8][pc + 4]; al[mi][3] = AsL[ar + 8][pc + 4];
            }
#pragma unroll
            for (int ni = 0; ni < 4; ni++) {
                int bc = wn * 32 + ni * 8 + g;
                int pr = kk * 8 + t;
                uint32_t bh0 = BsH[pr][bc], bh1 = BsH[pr + 4][bc];
                uint32_t bl0 = BsL[pr][bc], bl1 = BsL[pr + 4][bc];
#pragma unroll
                for (int mi = 0; mi < 4; mi++) {
                    mma_bf16(acc[mi][ni], ah[mi], bh0, bh1);
                    mma_bf16(acc[mi][ni], al[mi], bh0, bh1);
                    mma_bf16(acc[mi][ni], ah[mi], bl0, bl1);
                }
            }
        }
        __syncthreads();
    }

    // epilogue: c0,c1 = (row g, cols 2t,2t+1); c2,c3 = row g+8
#pragma unroll
    for (int mi = 0; mi < 4; mi++) {
#pragma unroll
        for (int ni = 0; ni < 4; ni++) {
            int r0 = cRow * 128 + wm * 64 + mi * 16 + g;
            int c0 = cCol * 128 + wn * 32 + ni * 8 + 2 * t;
            float b0 = bias ? bias[c0] : 0.f;
            float b1 = bias ? bias[c0 + 1] : 0.f;
            float2 v01 = make_float2(acc[mi][ni][0] + b0, acc[mi][ni][1] + b1);
            float2 v23 = make_float2(acc[mi][ni][2] + b0, acc[mi][ni][3] + b1);
            *(float2*)&C[(size_t)r0 * N + c0] = v01;
            *(float2*)&C[(size_t)(r0 + 8) * N + c0] = v23;
        }
    }
}

// ---------------- K2: orientation bins ----------------
// grid (NSPLIT, H, B), block 128 (thread = k); 128 x per block
__global__ __launch_bounds__(128) void k2_scores()
{
    int k = threadIdx.x;
    int xc = blockIdx.x, h = blockIdx.y, b = blockIdx.z;
    int bh = b * H_ + h;
    int xbase = xc * (XL / NSPLIT);
    __shared__ float kx_sh[64 * 32];
    __shared__ unsigned pk_sh[128 * 33];

    float4 kq4[8];
    const float4* kqp = (const float4*)&g_QKVk[((size_t)(b * KL + k)) * TDIM + h * HD];
#pragma unroll
    for (int i = 0; i < 8; i++) kq4[i] = kqp[i];

    float bins[8];
#pragma unroll
    for (int o = 0; o < 8; o++) bins[o] = 0.f;

    const unsigned* pkg = (const unsigned*)&g_pack[(size_t)bh * KL * XL];

    for (int c = 0; c < 2; c++) {
        int xs = xbase + c * 64;
        __syncthreads();
        for (int g = threadIdx.x; g < 512; g += 128) {
            int row = g >> 3, c4 = g & 7;
            ((float4*)kx_sh)[g] =
                *(const float4*)&g_QKVx[((size_t)(b * XL + xs + row)) * TDIM + DIM + h * HD + c4 * 4];
        }
        for (int g = threadIdx.x; g < 128 * 32; g += 128) {
            int row = g >> 5, col = g & 31;
            pk_sh[row * 33 + col] = pkg[(size_t)row * (XL / 2) + (xs >> 1) + col];
        }
        __syncthreads();
        const unsigned short* prow = (const unsigned short*)&pk_sh[k * 33];
        for (int j0 = 0; j0 < 64; j0 += 4) {
#pragma unroll
            for (int jj = 0; jj < 4; jj++) {
                const float4* kx4 = (const float4*)&kx_sh[(j0 + jj) * 32];
                float a = 0.f;
#pragma unroll
                for (int d = 0; d < 8; d++) {
                    float4 v = kx4[d];
                    a += v.x * kq4[d].x + v.y * kq4[d].y + v.z * kq4[d].z + v.w * kq4[d].w;
                }
                float as = fabsf(a * SCALE);
                int pv = (prow[j0 + jj] >> 7) & 7;
#pragma unroll
                for (int o = 0; o < 8; o++) bins[o] += (pv == o) ? as : 0.f;
            }
        }
    }
    float* orow = &g_oriP[((size_t)xc * B_ * H_ * KL + bh * KL + k) * 8];
#pragma unroll
    for (int o = 0; o < 8; o++) orow[o] = bins[o];
}

// ---------------- K2c: reduce slices + argmax ----------------
__global__ void k2_argmax()
{
    int idx = blockIdx.x * blockDim.x + threadIdx.x;
    if (idx >= B_ * H_ * KL) return;
    float s[8];
#pragma unroll
    for (int o = 0; o < 8; o++) s[o] = 0.f;
    for (int xc = 0; xc < NSPLIT; xc++) {
        const float* p = &g_oriP[((size_t)xc * B_ * H_ * KL + idx) * 8];
#pragma unroll
        for (int o = 0; o < 8; o++) s[o] += p[o];
    }
    int best = 0;
    float bv = s[0];
#pragma unroll
    for (int p = 1; p < 8; p++)
        if (s[p] > bv) { bv = s[p]; best = p; }
    g_mo[idx] = best;
}

// ---------------- K3: kernel->x attention (no-max softmax, 32 splits) -----
// grid (NSPLIT, H, B), block 128 (thread = k)
__global__ __launch_bounds__(128) void k3_kattn(
    const float* __restrict__ dis_embed, const float* __restrict__ polar_emb)
{
    int k = threadIdx.x;
    int xs = blockIdx.x, h = blockIdx.y, b = blockIdx.z;
    int bh = b * H_ + h;
    __shared__ float kx_sh[64 * 32];
    __shared__ float V_sh[64 * 32];
    __shared__ unsigned pk_sh[128 * 33];
    __shared__ float de_sh[NDIS];
    __shared__ float pe_sh[8];
    if (k < NDIS) de_sh[k] = dis_embed[k * H_ + h];
    if (k < 8) pe_sh[k] = polar_emb[k];
    int mo = g_mo[bh * KL + k];

    float4 kq4[8];
    const float4* kqp = (const float4*)&g_QKVk[((size_t)(b * KL + k)) * TDIM + h * HD];
#pragma unroll
    for (int i = 0; i < 8; i++) kq4[i] = kqp[i];

    const unsigned* pkg = (const unsigned*)&g_pack[(size_t)bh * KL * XL];

    float l = 0.f;
    float acc[32];
#pragma unroll
    for (int d = 0; d < 32; d++) acc[d] = 0.f;

    int xbase = xs * (XL / NSPLIT);
    for (int c = 0; c < 2; c++) {
        int x0 = xbase + c * 64;
        __syncthreads();
        for (int g = threadIdx.x; g < 512; g += 128) {
            int row = g >> 3, c4 = g & 7;
            size_t rb = ((size_t)(b * XL + x0 + row)) * TDIM + h * HD + c4 * 4;
            ((float4*)kx_sh)[g] = *(const float4*)&g_QKVx[rb + DIM];
            ((float4*)V_sh)[g]  = *(const float4*)&g_QKVx[rb + 2 * DIM];
        }
        for (int g = threadIdx.x; g < 128 * 32; g += 128) {
            int row = g >> 5, col = g & 31;
            pk_sh[row * 33 + col] = pkg[(size_t)row * (XL / 2) + (x0 >> 1) + col];
        }
        __syncthreads();
        const unsigned short* prow = (const unsigned short*)&pk_sh[k * 33];
        for (int j0 = 0; j0 < 64; j0 += 4) {
#pragma unroll
            for (int jj = 0; jj < 4; jj++) {
                int j = j0 + jj;
                const float4* kx4 = (const float4*)&kx_sh[j * 32];
                float a = 0.f;
#pragma unroll
                for (int d = 0; d < 8; d++) {
                    float4 v = kx4[d];
                    a += v.x * kq4[d].x + v.y * kq4[d].y + v.z * kq4[d].z + v.w * kq4[d].w;
                }
                unsigned short p = prow[j];
                float t = a * SCALE + de_sh[p & 127] + pe_sh[(((p >> 7) & 7) - mo) & 7];
                float w = (p >> 10) ? 0.f : __expf(t);
                l += w;
                const float4* vp = (const float4*)&V_sh[j * 32];
#pragma unroll
                for (int d = 0; d < 8; d++) {
                    float4 v = vp[d];
                    acc[d * 4 + 0] += w * v.x;
                    acc[d * 4 + 1] += w * v.y;
                    acc[d * 4 + 2] += w * v.z;
                    acc[d * 4 + 3] += w * v.w;
                }
            }
        }
    }
    float* pp = &g_part[(((size_t)bh * NSPLIT + xs) * KL + k) * 33];
    pp[0] = l;
#pragma unroll
    for (int d = 0; d < 32; d++) pp[1 + d] = acc[d];
}

// ---------------- K3c: combine x-splits -> preK ----------------
__global__ void k3_combine()
{
    int idx = blockIdx.x * blockDim.x + threadIdx.x;
    if (idx >= B_ * H_ * KL * 32) return;
    int d = idx & 31;
    int k = (idx >> 5) & (KL - 1);
    int bh = idx >> 12;
    int h = bh % H_, b = bh / H_;
    const float* base = &g_part[((size_t)bh * NSPLIT) * KL * 33 + (size_t)k * 33];
    float L = 0.f, A = 0.f;
    const size_t SSTR = (size_t)KL * 33;
#pragma unroll 8
    for (int s = 0; s < NSPLIT; s++) {
        L += base[s * SSTR];
        A += base[s * SSTR + 1 + d];
    }
    g_preK[((size_t)b * KL + k) * DIM + h * HD + d] = A / L;
}

// ---------------- K4: x->kernel attention (no-max softmax) ----------------
// grid (XL/128, H, B), block 128 (thread = x)
__global__ __launch_bounds__(128) void k4_xattn(
    const float* __restrict__ dis_embed, const float* __restrict__ polar_emb)
{
    __shared__ float kk_sh[KL * HD];
    __shared__ float kv_sh[KL * HD];
    __shared__ float de_sh[NDIS];
    __shared__ float pe_sh[8];
    __shared__ int   mo_sh[KL];
    int tid = threadIdx.x;
    int xc = blockIdx.x, h = blockIdx.y, b = blockIdx.z;
    int bh = b * H_ + h;

    for (int g = tid; g < KL * HD / 4; g += 128) {
        int row = g >> 3, c4 = g & 7;
        ((float4*)kk_sh)[g] =
            *(const float4*)&g_QKVk[((size_t)(b * KL + row)) * TDIM + DIM + h * HD + c4 * 4];
        ((float4*)kv_sh)[g] =
            *(const float4*)&g_QKVk[((size_t)(b * KL + row)) * TDIM + 2 * DIM + h * HD + c4 * 4];
    }
    if (tid < NDIS) de_sh[tid] = dis_embed[tid * H_ + h];
    if (tid < 8) pe_sh[tid] = polar_emb[tid];
    if (tid < KL) mo_sh[tid] = g_mo[bh * KL + tid];
    __syncthreads();

    int x = xc * 128 + tid;
    float4 q4[8];
    const float4* qp = (const float4*)&g_QKVx[((size_t)(b * XL + x)) * TDIM + h * HD];
#pragma unroll
    for (int i = 0; i < 8; i++) q4[i] = qp[i];
    const unsigned short* pk = &g_pack[(size_t)bh * KL * XL + x];

    float l = 0.f;
    float acc[32];
#pragma unroll
    for (int d = 0; d < 32; d++) acc[d] = 0.f;

    for (int k0 = 0; k0 < KL; k0 += 4) {
#pragma unroll
        for (int ki = 0; ki < 4; ki++) {
            int kidx = k0 + ki;
            const float4* kkp = (const float4*)&kk_sh[kidx * HD];
            float s = 0.f;
#pragma unroll
            for (int d = 0; d < 8; d++) {
                float4 a = kkp[d];
                s += a.x * q4[d].x + a.y * q4[d].y + a.z * q4[d].z + a.w * q4[d].w;
            }
            unsigned short p = pk[(size_t)kidx * XL];
            float t = s * SCALE + de_sh[p & 127] + pe_sh[(((p >> 7) & 7) - mo_sh[kidx]) & 7];
            float w = (p >> 10) ? 0.f : __expf(t);
            l += w;
            const float4* vp = (const float4*)&kv_sh[kidx * HD];
#pragma unroll
            for (int d = 0; d < 8; d++) {
                float4 v = vp[d];
                acc[d * 4 + 0] += w * v.x;
                acc[d * 4 + 1] += w * v.y;
                acc[d * 4 + 2] += w * v.z;
                acc[d * 4 + 3] += w * v.w;
            }
        }
    }
    float invl = 1.f / l;
    float* out = &g_preX[((size_t)(b * XL + x)) * DIM + h * HD];
#pragma unroll
    for (int d = 0; d < 8; d++) {
        float4 v;
        v.x = acc[d * 4 + 0] * invl;
        v.y = acc[d * 4 + 1] * invl;
        v.z = acc[d * 4 + 2] * invl;
        v.w = acc[d * 4 + 3] * invl;
        *(float4*)&out[d * 4] = v;
    }
}

// ---------------- host launcher ----------------
extern "C" void kernel_launch(void* const* d_in, const int* in_sizes, int n_in,
                              void* d_out, int out_size)
{
    const float* x     = (const float*)d_in[0];
    const float* kern  = (const float*)d_in[1];
    const int*   rd    = (const int*)d_in[2];
    const int*   polar = (const int*)d_in[3];
    const void*  mask  = d_in[4];
    const float* Wqkv  = (const float*)d_in[5];
    const float* dis   = (const float*)d_in[6];
    const float* pemb  = (const float*)d_in[7];
    const float* Wproj = (const float*)d_in[8];
    const float* bproj = (const float*)d_in[9];
    float* out = (float*)d_out;

    float* pQKVx; cudaGetSymbolAddress((void**)&pQKVx, g_QKVx);
    float* pQKVk; cudaGetSymbolAddress((void**)&pQKVk, g_QKVk);
    float* pPreX; cudaGetSymbolAddress((void**)&pPreX, g_preX);
    float* pPreK; cudaGetSymbolAddress((void**)&pPreK, g_preK);

    // mask dtype probe + packed bias table
    det_reset<<<1, 32>>>();
    det_scan<<<256, 256>>>((const unsigned*)mask);
    pack16<<<dim3(XL / 64, KL / 32, B_), dim3(32, 8)>>>(mask, rd, polar);

    // QKV projections (bf16x3 tensor cores)
    gemm_bf16x3<<<dim3(TDIM / 128, (B_ * XL) / 128), 256>>>(x, Wqkv, nullptr, pQKVx, B_ * XL, TDIM, DIM);
    gemm_bf16x3<<<dim3(TDIM / 128, (B_ * KL) / 128), 256>>>(kern, Wqkv, nullptr, pQKVk, B_ * KL, TDIM, DIM);

    // orientation bins + argmax
    k2_scores<<<dim3(NSPLIT, H_, B_), 128>>>();
    k2_argmax<<<(B_ * H_ * KL + 255) / 256, 256>>>();

    // kernel->x attention
    k3_kattn<<<dim3(NSPLIT, H_, B_), 128>>>(dis, pemb);
    k3_combine<<<(B_ * H_ * KL * 32 + 255) / 256, 256>>>();

    // x->kernel attention
    k4_xattn<<<dim3(XL / 128, H_, B_), 128>>>(dis, pemb);

    // output projections
    gemm_bf16x3<<<dim3(DIM / 128, (B_ * XL) / 128), 256>>>(pPreX, Wproj, bproj, out, B_ * XL, DIM, DIM);
    gemm_bf16x3<<<dim3(DIM / 128, (B_ * KL) / 128), 256>>>(pPreK, Wproj, bproj, out + (size_t)B_ * XL * DIM, B_ * KL, DIM, DIM);
}

// round 10
// speedup vs baseline: 1.1923x; 1.0336x over previous
#include <cuda_runtime.h>
#include <cuda_bf16.h>
#include <cstdint>

#define B_    4
#define KL    128
#define XL    4096
#define DIM   256
#define H_    8
#define HD    32
#define PB    8
#define NDIS  66
#define TDIM  768           // 3*DIM
#define SCALE 0.17677669529663687f
#define NMASK (B_ * H_ * XL * KL)
#define NSPLIT 32           // x-splits for k2/k3

// ---------------- scratch (device globals) ----------------
__device__ float    g_QKVx[B_ * XL * TDIM];
__device__ float    g_QKVk[B_ * KL * TDIM];
__device__ unsigned short g_pack[(size_t)NMASK];       // (b,h,k,x): rd | polar<<7 | mask<<10
__device__ float    g_oriP[NSPLIT * B_ * H_ * KL * PB];
__device__ int      g_mo[B_ * H_ * KL];
__device__ float    g_part[(size_t)B_ * H_ * NSPLIT * KL * 33];  // (l, acc[32])
__device__ unsigned g_flags;
// pre-split bf16 hi/lo operand storage (u32 = packed bf16x2 along K)
__device__ uint32_t g_xhi[B_ * XL * DIM / 2],  g_xlo[B_ * XL * DIM / 2];
__device__ uint32_t g_khi[B_ * KL * DIM / 2],  g_klo[B_ * KL * DIM / 2];
__device__ uint32_t g_wqh[(DIM / 2) * TDIM],   g_wql[(DIM / 2) * TDIM];
__device__ uint32_t g_wph[(DIM / 2) * DIM],    g_wpl[(DIM / 2) * DIM];
__device__ uint32_t g_pXh[B_ * XL * DIM / 2],  g_pXl[B_ * XL * DIM / 2];
__device__ uint32_t g_pKh[B_ * KL * DIM / 2],  g_pKl[B_ * KL * DIM / 2];

// ---------------- bf16 split helper ----------------
__device__ __forceinline__ uint32_t split_pack(float x0, float x1, uint32_t& lo_pack)
{
    __nv_bfloat16 h0 = __float2bfloat16(x0);
    __nv_bfloat16 h1 = __float2bfloat16(x1);
    float l0 = x0 - __bfloat162float(h0);
    float l1 = x1 - __bfloat162float(h1);
    __nv_bfloat162 hp = __halves2bfloat162(h0, h1);
    __nv_bfloat162 lp = __halves2bfloat162(__float2bfloat16(l0), __float2bfloat16(l1));
    lo_pack = *(uint32_t*)&lp;
    return *(uint32_t*)&hp;
}

// ---------------- mask dtype probe ----------------
__global__ void det_reset() { if (threadIdx.x == 0) g_flags = 0u; }

__global__ void det_scan(const unsigned* __restrict__ w)
{
    int i = blockIdx.x * blockDim.x + threadIdx.x;
    unsigned v = w[i];
    unsigned f = 0;
    if (v == 0x3F800000u) f |= 1u;
    else if (v != 0u && v != 1u) f |= 2u;
    for (int o = 16; o > 0; o >>= 1) f |= __shfl_xor_sync(0xffffffffu, f, o);
    if ((threadIdx.x & 31) == 0 && f) atomicOr(&g_flags, f);
}

// ---------------- presplit kernels ----------------
// A-style: pack along contiguous K (row-major [M,K] -> [M,K/2] u32)
__global__ void presplitA(const float* __restrict__ A,
                          uint32_t* __restrict__ hi, uint32_t* __restrict__ lo, int n)
{
    int i = blockIdx.x * blockDim.x + threadIdx.x;
    if (i >= n) return;
    float2 v = *(const float2*)&A[2 * i];
    uint32_t l, h = split_pack(v.x, v.y, l);
    hi[i] = h; lo[i] = l;
}

// B-style: pack pairs of K-rows ([K,N] -> [K/2,N] u32)
__global__ void presplitB(const float* __restrict__ Bm,
                          uint32_t* __restrict__ hi, uint32_t* __restrict__ lo, int N, int n)
{
    int i = blockIdx.x * blockDim.x + threadIdx.x;
    if (i >= n) return;
    int p = i / N, c = i - p * N;
    uint32_t l, h = split_pack(Bm[(size_t)(2 * p) * N + c], Bm[(size_t)(2 * p + 1) * N + c], l);
    hi[i] = h; lo[i] = l;
}

// ---------------- pack16: rd+polar+mask(transposed) -> u16 (b,h,k,x) ------
__global__ void pack16(const void* __restrict__ mask,
                       const int* __restrict__ rd, const int* __restrict__ polar)
{
    __shared__ unsigned short rp_sh[32][66];
    __shared__ uint8_t m_sh[64][36];
    unsigned flags = g_flags;
    int mode = (flags & 1u) ? 2 : ((flags & 2u) ? 0 : 1);
    int x0 = blockIdx.x * 64, k0 = blockIdx.y * 32, b = blockIdx.z;
    int tx = threadIdx.x, ty = threadIdx.y;

#pragma unroll
    for (int ki = ty; ki < 32; ki += 8) {
        size_t rowb = ((size_t)(b * KL + k0 + ki)) * XL + x0;
#pragma unroll
        for (int xx = tx; xx < 64; xx += 32) {
            int r = rd[rowb + xx];
            int p = polar[rowb + xx];
            rp_sh[ki][xx] = (unsigned short)(r | (p << 7));
        }
    }
    for (int h = 0; h < H_; h++) {
        size_t mb = ((size_t)((b * H_ + h)) * XL + x0) * KL + k0;
#pragma unroll
        for (int xi = ty; xi < 64; xi += 8) {
            uint8_t v;
            if (mode == 1)      v = ((const int*)mask)[mb + (size_t)xi * KL + tx] != 0;
            else if (mode == 2) v = ((const float*)mask)[mb + (size_t)xi * KL + tx] != 0.f;
            else                v = ((const uint8_t*)mask)[mb + (size_t)xi * KL + tx] != 0;
            m_sh[xi][tx] = v;
        }
        __syncthreads();
        size_t ob = ((size_t)((b * H_ + h) * KL + k0)) * XL + x0;
#pragma unroll
        for (int ki = ty; ki < 32; ki += 8)
#pragma unroll
            for (int xx = tx; xx < 64; xx += 32)
                g_pack[ob + (size_t)ki * XL + xx] =
                    (unsigned short)(rp_sh[ki][xx] | ((unsigned short)m_sh[xx][ki] << 10));
        __syncthreads();
    }
}

// ---------------- bf16x3 GEMM on pre-split operands -----------------------
__device__ __forceinline__ void mma_bf16(float* c, const uint32_t* a, uint32_t b0, uint32_t b1)
{
    asm("mma.sync.aligned.m16n8k16.row.col.f32.bf16.bf16.f32 "
        "{%0,%1,%2,%3}, {%4,%5,%6,%7}, {%8,%9}, {%0,%1,%2,%3};"
        : "+f"(c[0]), "+f"(c[1]), "+f"(c[2]), "+f"(c[3])
        : "r"(a[0]), "r"(a[1]), "r"(a[2]), "r"(a[3]), "r"(b0), "r"(b1));
}

// Block 128x128, BK=32 (16 pairs), 256 threads (8 warps: 2(m) x 4(n))
__global__ __launch_bounds__(256, 2) void gemm_pre(
    const uint32_t* __restrict__ Ahi, const uint32_t* __restrict__ Alo,
    const uint32_t* __restrict__ Bhi, const uint32_t* __restrict__ Blo,
    const float* __restrict__ bias, float* __restrict__ C,
    int M, int N, int K)
{
    __shared__ uint32_t AsH[128][20];
    __shared__ uint32_t AsL[128][20];
    __shared__ uint32_t BsH[16][136];
    __shared__ uint32_t BsL[16][136];
    int tid = threadIdx.x;
    int wid = tid >> 5, lane = tid & 31;
    int g = lane >> 2, t = lane & 3;
    int wm = wid & 1, wn = wid >> 1;
    int cCol = blockIdx.x, cRow = blockIdx.y;
    const int KP = K >> 1;

    float acc[4][4][4];
#pragma unroll
    for (int i = 0; i < 4; i++)
#pragma unroll
        for (int j = 0; j < 4; j++)
#pragma unroll
            for (int c = 0; c < 4; c++) acc[i][j][c] = 0.f;

    for (int k0p = 0; k0p < KP; k0p += 16) {
        // A tile: 128 rows x 16 pairs (uint2 loads)
#pragma unroll
        for (int j = 0; j < 4; j++) {
            int f = tid + 256 * j;
            int r = f >> 3, p2 = (f & 7) * 2;
            size_t off = (size_t)(cRow * 128 + r) * KP + k0p + p2;
            uint2 h = *(const uint2*)&Ahi[off];
            uint2 l = *(const uint2*)&Alo[off];
            AsH[r][p2] = h.x; AsH[r][p2 + 1] = h.y;
            AsL[r][p2] = l.x; AsL[r][p2 + 1] = l.y;
        }
        // B tile: 16 pair-rows x 128 cols (uint2 loads)
#pragma unroll
        for (int j = 0; j < 4; j++) {
            int f = tid + 256 * j;
            int pr = f >> 6, c2 = (f & 63) * 2;
            size_t off = (size_t)(k0p + pr) * N + cCol * 128 + c2;
            uint2 h = *(const uint2*)&Bhi[off];
            uint2 l = *(const uint2*)&Blo[off];
            BsH[pr][c2] = h.x; BsH[pr][c2 + 1] = h.y;
            BsL[pr][c2] = l.x; BsL[pr][c2 + 1] = l.y;
        }
        __syncthreads();

#pragma unroll
        for (int kk = 0; kk < 2; kk++) {
            uint32_t ah[4][4], al[4][4];
#pragma unroll
            for (int mi = 0; mi < 4; mi++) {
                int ar = wm * 64 + mi * 16 + g;
                int pc = kk * 8 + t;
                ah[mi][0] = AsH[ar][pc];         al[mi][0] = AsL[ar][pc];
                ah[mi][1] = AsH[ar + 8][pc];     al[mi][1] = AsL[ar + 8][pc];
                ah[mi][2] = AsH[ar][pc + 4];     al[mi][2] = AsL[ar][pc + 4];
                ah[mi][3] = AsH[ar + 8][pc + 4]; al[mi][3] = AsL[ar + 8][pc + 4];
            }
#pragma unroll
            for (int ni = 0; ni < 4; ni++) {
                int bc = wn * 32 + ni * 8 + g;
                int pr = kk * 8 + t;
                uint32_t bh0 = BsH[pr][bc], bh1 = BsH[pr + 4][bc];
                uint32_t bl0 = BsL[pr][bc], bl1 = BsL[pr + 4][bc];
#pragma unroll
                for (int mi = 0; mi < 4; mi++) {
                    mma_bf16(acc[mi][ni], ah[mi], bh0, bh1);
                    mma_bf16(acc[mi][ni], al[mi], bh0, bh1);
                    mma_bf16(acc[mi][ni], ah[mi], bl0, bl1);
                }
            }
        }
        __syncthreads();
    }

#pragma unroll
    for (int mi = 0; mi < 4; mi++) {
#pragma unroll
        for (int ni = 0; ni < 4; ni++) {
            int r0 = cRow * 128 + wm * 64 + mi * 16 + g;
            int c0 = cCol * 128 + wn * 32 + ni * 8 + 2 * t;
            float b0 = bias ? bias[c0] : 0.f;
            float b1 = bias ? bias[c0 + 1] : 0.f;
            float2 v01 = make_float2(acc[mi][ni][0] + b0, acc[mi][ni][1] + b1);
            float2 v23 = make_float2(acc[mi][ni][2] + b0, acc[mi][ni][3] + b1);
            *(float2*)&C[(size_t)r0 * N + c0] = v01;
            *(float2*)&C[(size_t)(r0 + 8) * N + c0] = v23;
        }
    }
}

// ---------------- K2: orientation bins ----------------
__global__ __launch_bounds__(128) void k2_scores()
{
    int k = threadIdx.x;
    int xc = blockIdx.x, h = blockIdx.y, b = blockIdx.z;
    int bh = b * H_ + h;
    int xbase = xc * (XL / NSPLIT);
    __shared__ float kx_sh[64 * 32];
    __shared__ unsigned pk_sh[128 * 33];

    float4 kq4[8];
    const float4* kqp = (const float4*)&g_QKVk[((size_t)(b * KL + k)) * TDIM + h * HD];
#pragma unroll
    for (int i = 0; i < 8; i++) kq4[i] = kqp[i];

    float bins[8];
#pragma unroll
    for (int o = 0; o < 8; o++) bins[o] = 0.f;

    const unsigned* pkg = (const unsigned*)&g_pack[(size_t)bh * KL * XL];

    for (int c = 0; c < 2; c++) {
        int xs = xbase + c * 64;
        __syncthreads();
        for (int g = threadIdx.x; g < 512; g += 128) {
            int row = g >> 3, c4 = g & 7;
            ((float4*)kx_sh)[g] =
                *(const float4*)&g_QKVx[((size_t)(b * XL + xs + row)) * TDIM + DIM + h * HD + c4 * 4];
        }
        for (int g = threadIdx.x; g < 128 * 32; g += 128) {
            int row = g >> 5, col = g & 31;
            pk_sh[row * 33 + col] = pkg[(size_t)row * (XL / 2) + (xs >> 1) + col];
        }
        __syncthreads();
        const unsigned short* prow = (const unsigned short*)&pk_sh[k * 33];
        for (int j0 = 0; j0 < 64; j0 += 4) {
#pragma unroll
            for (int jj = 0; jj < 4; jj++) {
                const float4* kx4 = (const float4*)&kx_sh[(j0 + jj) * 32];
                float a = 0.f;
#pragma unroll
                for (int d = 0; d < 8; d++) {
                    float4 v = kx4[d];
                    a += v.x * kq4[d].x + v.y * kq4[d].y + v.z * kq4[d].z + v.w * kq4[d].w;
                }
                float as = fabsf(a * SCALE);
                int pv = (prow[j0 + jj] >> 7) & 7;
#pragma unroll
                for (int o = 0; o < 8; o++) bins[o] += (pv == o) ? as : 0.f;
            }
        }
    }
    float* orow = &g_oriP[((size_t)xc * B_ * H_ * KL + bh * KL + k) * 8];
#pragma unroll
    for (int o = 0; o < 8; o++) orow[o] = bins[o];
}

// ---------------- K2c: reduce slices + argmax ----------------
__global__ void k2_argmax()
{
    int idx = blockIdx.x * blockDim.x + threadIdx.x;
    if (idx >= B_ * H_ * KL) return;
    float s[8];
#pragma unroll
    for (int o = 0; o < 8; o++) s[o] = 0.f;
    for (int xc = 0; xc < NSPLIT; xc++) {
        const float* p = &g_oriP[((size_t)xc * B_ * H_ * KL + idx) * 8];
#pragma unroll
        for (int o = 0; o < 8; o++) s[o] += p[o];
    }
    int best = 0;
    float bv = s[0];
#pragma unroll
    for (int p = 1; p < 8; p++)
        if (s[p] > bv) { bv = s[p]; best = p; }
    g_mo[idx] = best;
}

// ---------------- K3: kernel->x attention (no-max softmax, 32 splits) -----
__global__ __launch_bounds__(128) void k3_kattn(
    const float* __restrict__ dis_embed, const float* __restrict__ polar_emb)
{
    int k = threadIdx.x;
    int xs = blockIdx.x, h = blockIdx.y, b = blockIdx.z;
    int bh = b * H_ + h;
    __shared__ float kx_sh[64 * 32];
    __shared__ float V_sh[64 * 32];
    __shared__ unsigned pk_sh[128 * 33];
    __shared__ float de_sh[NDIS];
    __shared__ float pe_sh[8];
    if (k < NDIS) de_sh[k] = dis_embed[k * H_ + h];
    if (k < 8) pe_sh[k] = polar_emb[k];
    int mo = g_mo[bh * KL + k];

    float4 kq4[8];
    const float4* kqp = (const float4*)&g_QKVk[((size_t)(b * KL + k)) * TDIM + h * HD];
#pragma unroll
    for (int i = 0; i < 8; i++) kq4[i] = kqp[i];

    const unsigned* pkg = (const unsigned*)&g_pack[(size_t)bh * KL * XL];

    float l = 0.f;
    float acc[32];
#pragma unroll
    for (int d = 0; d < 32; d++) acc[d] = 0.f;

    int xbase = xs * (XL / NSPLIT);
    for (int c = 0; c < 2; c++) {
        int x0 = xbase + c * 64;
        __syncthreads();
        for (int g = threadIdx.x; g < 512; g += 128) {
            int row = g >> 3, c4 = g & 7;
            size_t rb = ((size_t)(b * XL + x0 + row)) * TDIM + h * HD + c4 * 4;
            ((float4*)kx_sh)[g] = *(const float4*)&g_QKVx[rb + DIM];
            ((float4*)V_sh)[g]  = *(const float4*)&g_QKVx[rb + 2 * DIM];
        }
        for (int g = threadIdx.x; g < 128 * 32; g += 128) {
            int row = g >> 5, col = g & 31;
            pk_sh[row * 33 + col] = pkg[(size_t)row * (XL / 2) + (x0 >> 1) + col];
        }
        __syncthreads();
        const unsigned short* prow = (const unsigned short*)&pk_sh[k * 33];
        for (int j0 = 0; j0 < 64; j0 += 4) {
#pragma unroll
            for (int jj = 0; jj < 4; jj++) {
                int j = j0 + jj;
                const float4* kx4 = (const float4*)&kx_sh[j * 32];
                float a = 0.f;
#pragma unroll
                for (int d = 0; d < 8; d++) {
                    float4 v = kx4[d];
                    a += v.x * kq4[d].x + v.y * kq4[d].y + v.z * kq4[d].z + v.w * kq4[d].w;
                }
                unsigned short p = prow[j];
                float t = a * SCALE + de_sh[p & 127] + pe_sh[(((p >> 7) & 7) - mo) & 7];
                float w = (p >> 10) ? 0.f : __expf(t);
                l += w;
                const float4* vp = (const float4*)&V_sh[j * 32];
#pragma unroll
                for (int d = 0; d < 8; d++) {
                    float4 v = vp[d];
                    acc[d * 4 + 0] += w * v.x;
                    acc[d * 4 + 1] += w * v.y;
                    acc[d * 4 + 2] += w * v.z;
                    acc[d * 4 + 3] += w * v.w;
                }
            }
        }
    }
    float* pp = &g_part[(((size_t)bh * NSPLIT + xs) * KL + k) * 33];
    pp[0] = l;
#pragma unroll
    for (int d = 0; d < 32; d++) pp[1 + d] = acc[d];
}

// ---------------- K3c: combine x-splits -> preK (bf16 hi/lo out) ----------
// thread = (bh, k, dpair); 65536 threads
__global__ void k3_combine()
{
    int idx = blockIdx.x * blockDim.x + threadIdx.x;
    if (idx >= B_ * H_ * KL * 16) return;
    int d2 = idx & 15;
    int k = (idx >> 4) & (KL - 1);
    int bh = idx >> 11;
    int h = bh % H_, b = bh / H_;
    const float* base = &g_part[((size_t)bh * NSPLIT) * KL * 33 + (size_t)k * 33];
    float L = 0.f, A0 = 0.f, A1 = 0.f;
    const size_t SSTR = (size_t)KL * 33;
#pragma unroll 8
    for (int s = 0; s < NSPLIT; s++) {
        L  += base[s * SSTR];
        A0 += base[s * SSTR + 1 + 2 * d2];
        A1 += base[s * SSTR + 2 + 2 * d2];
    }
    float invL = 1.f / L;
    uint32_t lo, hi = split_pack(A0 * invL, A1 * invL, lo);
    size_t o = ((size_t)b * KL + k) * (DIM / 2) + h * (HD / 2) + d2;
    g_pKh[o] = hi;
    g_pKl[o] = lo;
}

// ---------------- K4: x->kernel attention (bf16 hi/lo out) ----------------
__global__ __launch_bounds__(128) void k4_xattn(
    const float* __restrict__ dis_embed, const float* __restrict__ polar_emb)
{
    __shared__ float kk_sh[KL * HD];
    __shared__ float kv_sh[KL * HD];
    __shared__ float de_sh[NDIS];
    __shared__ float pe_sh[8];
    __shared__ int   mo_sh[KL];
    int tid = threadIdx.x;
    int xc = blockIdx.x, h = blockIdx.y, b = blockIdx.z;
    int bh = b * H_ + h;

    for (int g = tid; g < KL * HD / 4; g += 128) {
        int row = g >> 3, c4 = g & 7;
        ((float4*)kk_sh)[g] =
            *(const float4*)&g_QKVk[((size_t)(b * KL + row)) * TDIM + DIM + h * HD + c4 * 4];
        ((float4*)kv_sh)[g] =
            *(const float4*)&g_QKVk[((size_t)(b * KL + row)) * TDIM + 2 * DIM + h * HD + c4 * 4];
    }
    if (tid < NDIS) de_sh[tid] = dis_embed[tid * H_ + h];
    if (tid < 8) pe_sh[tid] = polar_emb[tid];
    if (tid < KL) mo_sh[tid] = g_mo[bh * KL + tid];
    __syncthreads();

    int x = xc * 128 + tid;
    float4 q4[8];
    const float4* qp = (const float4*)&g_QKVx[((size_t)(b * XL + x)) * TDIM + h * HD];
#pragma unroll
    for (int i = 0; i < 8; i++) q4[i] = qp[i];
    const unsigned short* pk = &g_pack[(size_t)bh * KL * XL + x];

    float l = 0.f;
    float acc[32];
#pragma unroll
    for (int d = 0; d < 32; d++) acc[d] = 0.f;

    for (int k0 = 0; k0 < KL; k0 += 4) {
#pragma unroll
        for (int ki = 0; ki < 4; ki++) {
            int kidx = k0 + ki;
            const float4* kkp = (const float4*)&kk_sh[kidx * HD];
            float s = 0.f;
#pragma unroll
            for (int d = 0; d < 8; d++) {
                float4 a = kkp[d];
                s += a.x * q4[d].x + a.y * q4[d].y + a.z * q4[d].z + a.w * q4[d].w;
            }
            unsigned short p = pk[(size_t)kidx * XL];
            float t = s * SCALE + de_sh[p & 127] + pe_sh[(((p >> 7) & 7) - mo_sh[kidx]) & 7];
            float w = (p >> 10) ? 0.f : __expf(t);
            l += w;
            const float4* vp = (const float4*)&kv_sh[kidx * HD];
#pragma unroll
            for (int d = 0; d < 8; d++) {
                float4 v = vp[d];
                acc[d * 4 + 0] += w * v.x;
                acc[d * 4 + 1] += w * v.y;
                acc[d * 4 + 2] += w * v.z;
                acc[d * 4 + 3] += w * v.w;
            }
        }
    }
    float invl = 1.f / l;
    size_t ob = ((size_t)(b * XL + x)) * (DIM / 2) + h * (HD / 2);
#pragma unroll
    for (int d2 = 0; d2 < 16; d2++) {
        uint32_t lo, hi = split_pack(acc[2 * d2] * invl, acc[2 * d2 + 1] * invl, lo);
        g_pXh[ob + d2] = hi;
        g_pXl[ob + d2] = lo;
    }
}

// ---------------- host launcher ----------------
extern "C" void kernel_launch(void* const* d_in, const int* in_sizes, int n_in,
                              void* d_out, int out_size)
{
    const float* x     = (const float*)d_in[0];
    const float* kern  = (const float*)d_in[1];
    const int*   rd    = (const int*)d_in[2];
    const int*   polar = (const int*)d_in[3];
    const void*  mask  = d_in[4];
    const float* Wqkv  = (const float*)d_in[5];
    const float* dis   = (const float*)d_in[6];
    const float* pemb  = (const float*)d_in[7];
    const float* Wproj = (const float*)d_in[8];
    const float* bproj = (const float*)d_in[9];
    float* out = (float*)d_out;

    float* pQKVx; cudaGetSymbolAddress((void**)&pQKVx, g_QKVx);
    float* pQKVk; cudaGetSymbolAddress((void**)&pQKVk, g_QKVk);
    uint32_t *pxh, *pxl, *pkh, *pkl, *pwqh, *pwql, *pwph, *pwpl, *pXh, *pXl, *pKh, *pKl;
    cudaGetSymbolAddress((void**)&pxh, g_xhi);  cudaGetSymbolAddress((void**)&pxl, g_xlo);
    cudaGetSymbolAddress((void**)&pkh, g_khi);  cudaGetSymbolAddress((void**)&pkl, g_klo);
    cudaGetSymbolAddress((void**)&pwqh, g_wqh); cudaGetSymbolAddress((void**)&pwql, g_wql);
    cudaGetSymbolAddress((void**)&pwph, g_wph); cudaGetSymbolAddress((void**)&pwpl, g_wpl);
    cudaGetSymbolAddress((void**)&pXh, g_pXh);  cudaGetSymbolAddress((void**)&pXl, g_pXl);
    cudaGetSymbolAddress((void**)&pKh, g_pKh);  cudaGetSymbolAddress((void**)&pKl, g_pKl);

    // mask dtype probe + packed bias table
    det_reset<<<1, 32>>>();
    det_scan<<<256, 256>>>((const unsigned*)mask);
    pack16<<<dim3(XL / 64, KL / 32, B_), dim3(32, 8)>>>(mask, rd, polar);

    // pre-split GEMM operands
    presplitA<<<(B_ * XL * DIM / 2 + 255) / 256, 256>>>(x, pxh, pxl, B_ * XL * DIM / 2);
    presplitA<<<(B_ * KL * DIM / 2 + 255) / 256, 256>>>(kern, pkh, pkl, B_ * KL * DIM / 2);
    presplitB<<<((DIM / 2) * TDIM + 255) / 256, 256>>>(Wqkv, pwqh, pwql, TDIM, (DIM / 2) * TDIM);
    presplitB<<<((DIM / 2) * DIM + 255) / 256, 256>>>(Wproj, pwph, pwpl, DIM, (DIM / 2) * DIM);

    // QKV projections (pre-split bf16x3 tensor cores)
    gemm_pre<<<dim3(TDIM / 128, (B_ * XL) / 128), 256>>>(pxh, pxl, pwqh, pwql, nullptr, pQKVx, B_ * XL, TDIM, DIM);
    gemm_pre<<<dim3(TDIM / 128, (B_ * KL) / 128), 256>>>(pkh, pkl, pwqh, pwql, nullptr, pQKVk, B_ * KL, TDIM, DIM);

    // orientation bins + argmax
    k2_scores<<<dim3(NSPLIT, H_, B_), 128>>>();
    k2_argmax<<<(B_ * H_ * KL + 255) / 256, 256>>>();

    // kernel->x attention
    k3_kattn<<<dim3(NSPLIT, H_, B_), 128>>>(dis, pemb);
    k3_combine<<<(B_ * H_ * KL * 16 + 255) / 256, 256>>>();

    // x->kernel attention
    k4_xattn<<<dim3(XL / 128, H_, B_), 128>>>(dis, pemb);

    // output projections
    gemm_pre<<<dim3(DIM / 128, (B_ * XL) / 128), 256>>>(pXh, pXl, pwph, pwpl, bproj, out, B_ * XL, DIM, DIM);
    gemm_pre<<<dim3(DIM / 128, (B_ * KL) / 128), 256>>>(pKh, pKl, pwph, pwpl, bproj, out + (size_t)B_ * XL * DIM, B_ * KL, DIM, DIM);
}

// round 11
// speedup vs baseline: 1.2073x; 1.0126x over previous
#include <cuda_runtime.h>
#include <cuda_bf16.h>
#include <cstdint>

#define B_    4
#define KL    128
#define XL    4096
#define DIM   256
#define H_    8
#define HD    32
#define PB    8
#define NDIS  66
#define TDIM  768           // 3*DIM
#define SCALE 0.17677669529663687f
#define NMASK (B_ * H_ * XL * KL)
#define NSPLIT 32           // x-splits for k2/k3

// ---------------- scratch (device globals) ----------------
__device__ float    g_QKVx[B_ * XL * TDIM];
__device__ float    g_QKVk[B_ * KL * TDIM];
__device__ unsigned short g_pack[(size_t)NMASK];       // (b,h,k,x): rd | polar<<7 | mask<<10
__device__ float    g_oriP[NSPLIT * B_ * H_ * KL * PB];
__device__ int      g_mo[B_ * H_ * KL];
__device__ float    g_part[(size_t)B_ * H_ * NSPLIT * KL * 33];  // (l, acc[32])
__device__ unsigned g_flags;
// pre-split bf16 hi/lo operand storage (u32 = packed bf16x2 along K)
__device__ uint32_t g_xhi[B_ * XL * DIM / 2],  g_xlo[B_ * XL * DIM / 2];
__device__ uint32_t g_khi[B_ * KL * DIM / 2],  g_klo[B_ * KL * DIM / 2];
__device__ uint32_t g_wqh[(DIM / 2) * TDIM],   g_wql[(DIM / 2) * TDIM];
__device__ uint32_t g_wph[(DIM / 2) * DIM],    g_wpl[(DIM / 2) * DIM];
__device__ uint32_t g_pXh[B_ * XL * DIM / 2],  g_pXl[B_ * XL * DIM / 2];
__device__ uint32_t g_pKh[B_ * KL * DIM / 2],  g_pKl[B_ * KL * DIM / 2];

// ---------------- f32x2 packed helpers ----------------
__device__ __forceinline__ uint64_t pk2(float lo, float hi)
{
    uint64_t r;
    asm("mov.b64 %0, {%1, %2};" : "=l"(r) : "f"(lo), "f"(hi));
    return r;
}
__device__ __forceinline__ void upk2(float& lo, float& hi, uint64_t v)
{
    asm("mov.b64 {%0, %1}, %2;" : "=f"(lo), "=f"(hi) : "l"(v));
}
__device__ __forceinline__ void fma2(uint64_t& d, uint64_t a, uint64_t b)
{
    asm("fma.rn.f32x2 %0, %1, %2, %0;" : "+l"(d) : "l"(a), "l"(b));
}

// ---------------- bf16 split helper ----------------
__device__ __forceinline__ uint32_t split_pack(float x0, float x1, uint32_t& lo_pack)
{
    __nv_bfloat16 h0 = __float2bfloat16(x0);
    __nv_bfloat16 h1 = __float2bfloat16(x1);
    float l0 = x0 - __bfloat162float(h0);
    float l1 = x1 - __bfloat162float(h1);
    __nv_bfloat162 hp = __halves2bfloat162(h0, h1);
    __nv_bfloat162 lp = __halves2bfloat162(__float2bfloat16(l0), __float2bfloat16(l1));
    lo_pack = *(uint32_t*)&lp;
    return *(uint32_t*)&hp;
}

// ---------------- mask dtype probe ----------------
__global__ void det_reset() { if (threadIdx.x == 0) g_flags = 0u; }

__global__ void det_scan(const unsigned* __restrict__ w)
{
    int i = blockIdx.x * blockDim.x + threadIdx.x;
    unsigned v = w[i];
    unsigned f = 0;
    if (v == 0x3F800000u) f |= 1u;
    else if (v != 0u && v != 1u) f |= 2u;
    for (int o = 16; o > 0; o >>= 1) f |= __shfl_xor_sync(0xffffffffu, f, o);
    if ((threadIdx.x & 31) == 0 && f) atomicOr(&g_flags, f);
}

// ---------------- presplit kernels ----------------
__global__ void presplitA(const float* __restrict__ A,
                          uint32_t* __restrict__ hi, uint32_t* __restrict__ lo, int n)
{
    int i = blockIdx.x * blockDim.x + threadIdx.x;
    if (i >= n) return;
    float2 v = *(const float2*)&A[2 * i];
    uint32_t l, h = split_pack(v.x, v.y, l);
    hi[i] = h; lo[i] = l;
}

__global__ void presplitB(const float* __restrict__ Bm,
                          uint32_t* __restrict__ hi, uint32_t* __restrict__ lo, int N, int n)
{
    int i = blockIdx.x * blockDim.x + threadIdx.x;
    if (i >= n) return;
    int p = i / N, c = i - p * N;
    uint32_t l, h = split_pack(Bm[(size_t)(2 * p) * N + c], Bm[(size_t)(2 * p + 1) * N + c], l);
    hi[i] = h; lo[i] = l;
}

// ---------------- pack16: rd+polar+mask(transposed) -> u16 (b,h,k,x) ------
__global__ void pack16(const void* __restrict__ mask,
                       const int* __restrict__ rd, const int* __restrict__ polar)
{
    __shared__ unsigned short rp_sh[32][66];
    __shared__ uint8_t m_sh[64][36];
    unsigned flags = g_flags;
    int mode = (flags & 1u) ? 2 : ((flags & 2u) ? 0 : 1);
    int x0 = blockIdx.x * 64, k0 = blockIdx.y * 32, b = blockIdx.z;
    int tx = threadIdx.x, ty = threadIdx.y;

#pragma unroll
    for (int ki = ty; ki < 32; ki += 8) {
        size_t rowb = ((size_t)(b * KL + k0 + ki)) * XL + x0;
#pragma unroll
        for (int xx = tx; xx < 64; xx += 32) {
            int r = rd[rowb + xx];
            int p = polar[rowb + xx];
            rp_sh[ki][xx] = (unsigned short)(r | (p << 7));
        }
    }
    for (int h = 0; h < H_; h++) {
        size_t mb = ((size_t)((b * H_ + h)) * XL + x0) * KL + k0;
#pragma unroll
        for (int xi = ty; xi < 64; xi += 8) {
            uint8_t v;
            if (mode == 1)      v = ((const int*)mask)[mb + (size_t)xi * KL + tx] != 0;
            else if (mode == 2) v = ((const float*)mask)[mb + (size_t)xi * KL + tx] != 0.f;
            else                v = ((const uint8_t*)mask)[mb + (size_t)xi * KL + tx] != 0;
            m_sh[xi][tx] = v;
        }
        __syncthreads();
        size_t ob = ((size_t)((b * H_ + h) * KL + k0)) * XL + x0;
#pragma unroll
        for (int ki = ty; ki < 32; ki += 8)
#pragma unroll
            for (int xx = tx; xx < 64; xx += 32)
                g_pack[ob + (size_t)ki * XL + xx] =
                    (unsigned short)(rp_sh[ki][xx] | ((unsigned short)m_sh[xx][ki] << 10));
        __syncthreads();
    }
}

// ---------------- bf16x3 GEMM on pre-split operands -----------------------
__device__ __forceinline__ void mma_bf16(float* c, const uint32_t* a, uint32_t b0, uint32_t b1)
{
    asm("mma.sync.aligned.m16n8k16.row.col.f32.bf16.bf16.f32 "
        "{%0,%1,%2,%3}, {%4,%5,%6,%7}, {%8,%9}, {%0,%1,%2,%3};"
        : "+f"(c[0]), "+f"(c[1]), "+f"(c[2]), "+f"(c[3])
        : "r"(a[0]), "r"(a[1]), "r"(a[2]), "r"(a[3]), "r"(b0), "r"(b1));
}

__global__ __launch_bounds__(256, 2) void gemm_pre(
    const uint32_t* __restrict__ Ahi, const uint32_t* __restrict__ Alo,
    const uint32_t* __restrict__ Bhi, const uint32_t* __restrict__ Blo,
    const float* __restrict__ bias, float* __restrict__ C,
    int M, int N, int K)
{
    __shared__ uint32_t AsH[128][20];
    __shared__ uint32_t AsL[128][20];
    __shared__ uint32_t BsH[16][136];
    __shared__ uint32_t BsL[16][136];
    int tid = threadIdx.x;
    int wid = tid >> 5, lane = tid & 31;
    int g = lane >> 2, t = lane & 3;
    int wm = wid & 1, wn = wid >> 1;
    int cCol = blockIdx.x, cRow = blockIdx.y;
    const int KP = K >> 1;

    float acc[4][4][4];
#pragma unroll
    for (int i = 0; i < 4; i++)
#pragma unroll
        for (int j = 0; j < 4; j++)
#pragma unroll
            for (int c = 0; c < 4; c++) acc[i][j][c] = 0.f;

    for (int k0p = 0; k0p < KP; k0p += 16) {
#pragma unroll
        for (int j = 0; j < 4; j++) {
            int f = tid + 256 * j;
            int r = f >> 3, p2 = (f & 7) * 2;
            size_t off = (size_t)(cRow * 128 + r) * KP + k0p + p2;
            uint2 h = *(const uint2*)&Ahi[off];
            uint2 l = *(const uint2*)&Alo[off];
            AsH[r][p2] = h.x; AsH[r][p2 + 1] = h.y;
            AsL[r][p2] = l.x; AsL[r][p2 + 1] = l.y;
        }
#pragma unroll
        for (int j = 0; j < 4; j++) {
            int f = tid + 256 * j;
            int pr = f >> 6, c2 = (f & 63) * 2;
            size_t off = (size_t)(k0p + pr) * N + cCol * 128 + c2;
            uint2 h = *(const uint2*)&Bhi[off];
            uint2 l = *(const uint2*)&Blo[off];
            BsH[pr][c2] = h.x; BsH[pr][c2 + 1] = h.y;
            BsL[pr][c2] = l.x; BsL[pr][c2 + 1] = l.y;
        }
        __syncthreads();

#pragma unroll
        for (int kk = 0; kk < 2; kk++) {
            uint32_t ah[4][4], al[4][4];
#pragma unroll
            for (int mi = 0; mi < 4; mi++) {
                int ar = wm * 64 + mi * 16 + g;
                int pc = kk * 8 + t;
                ah[mi][0] = AsH[ar][pc];         al[mi][0] = AsL[ar][pc];
                ah[mi][1] = AsH[ar + 8][pc];     al[mi][1] = AsL[ar + 8][pc];
                ah[mi][2] = AsH[ar][pc + 4];     al[mi][2] = AsL[ar][pc + 4];
                ah[mi][3] = AsH[ar + 8][pc + 4]; al[mi][3] = AsL[ar + 8][pc + 4];
            }
#pragma unroll
            for (int ni = 0; ni < 4; ni++) {
                int bc = wn * 32 + ni * 8 + g;
                int pr = kk * 8 + t;
                uint32_t bh0 = BsH[pr][bc], bh1 = BsH[pr + 4][bc];
                uint32_t bl0 = BsL[pr][bc], bl1 = BsL[pr + 4][bc];
#pragma unroll
                for (int mi = 0; mi < 4; mi++) {
                    mma_bf16(acc[mi][ni], ah[mi], bh0, bh1);
                    mma_bf16(acc[mi][ni], al[mi], bh0, bh1);
                    mma_bf16(acc[mi][ni], ah[mi], bl0, bl1);
                }
            }
        }
        __syncthreads();
    }

#pragma unroll
    for (int mi = 0; mi < 4; mi++) {
#pragma unroll
        for (int ni = 0; ni < 4; ni++) {
            int r0 = cRow * 128 + wm * 64 + mi * 16 + g;
            int c0 = cCol * 128 + wn * 32 + ni * 8 + 2 * t;
            float b0 = bias ? bias[c0] : 0.f;
            float b1 = bias ? bias[c0 + 1] : 0.f;
            float2 v01 = make_float2(acc[mi][ni][0] + b0, acc[mi][ni][1] + b1);
            float2 v23 = make_float2(acc[mi][ni][2] + b0, acc[mi][ni][3] + b1);
            *(float2*)&C[(size_t)r0 * N + c0] = v01;
            *(float2*)&C[(size_t)(r0 + 8) * N + c0] = v23;
        }
    }
}

// ---------------- K2: orientation bins (f32x2 scores) ----------------
__global__ __launch_bounds__(128) void k2_scores()
{
    int k = threadIdx.x;
    int xc = blockIdx.x, h = blockIdx.y, b = blockIdx.z;
    int bh = b * H_ + h;
    int xbase = xc * (XL / NSPLIT);
    __shared__ float kx_sh[64 * 32];
    __shared__ unsigned pk_sh[128 * 33];

    uint64_t kq2[16];
    {
        const uint64_t* kqp = (const uint64_t*)&g_QKVk[((size_t)(b * KL + k)) * TDIM + h * HD];
#pragma unroll
        for (int i = 0; i < 16; i++) kq2[i] = kqp[i];
    }

    float bins[8];
#pragma unroll
    for (int o = 0; o < 8; o++) bins[o] = 0.f;

    const unsigned* pkg = (const unsigned*)&g_pack[(size_t)bh * KL * XL];

    for (int c = 0; c < 2; c++) {
        int xs = xbase + c * 64;
        __syncthreads();
        for (int g = threadIdx.x; g < 512; g += 128) {
            int row = g >> 3, c4 = g & 7;
            ((float4*)kx_sh)[g] =
                *(const float4*)&g_QKVx[((size_t)(b * XL + xs + row)) * TDIM + DIM + h * HD + c4 * 4];
        }
        for (int g = threadIdx.x; g < 128 * 32; g += 128) {
            int row = g >> 5, col = g & 31;
            pk_sh[row * 33 + col] = pkg[(size_t)row * (XL / 2) + (xs >> 1) + col];
        }
        __syncthreads();
        const unsigned short* prow = (const unsigned short*)&pk_sh[k * 33];
        for (int j0 = 0; j0 < 64; j0 += 4) {
#pragma unroll
            for (int jj = 0; jj < 4; jj++) {
                const ulonglong2* kx2 = (const ulonglong2*)&kx_sh[(j0 + jj) * 32];
                uint64_t sa = 0;
#pragma unroll
                for (int d = 0; d < 8; d++) {
                    ulonglong2 v = kx2[d];
                    fma2(sa, kq2[2 * d], v.x);
                    fma2(sa, kq2[2 * d + 1], v.y);
                }
                float s0, s1;
                upk2(s0, s1, sa);
                float as = fabsf((s0 + s1) * SCALE);
                int pv = (prow[j0 + jj] >> 7) & 7;
#pragma unroll
                for (int o = 0; o < 8; o++) bins[o] += (pv == o) ? as : 0.f;
            }
        }
    }
    float* orow = &g_oriP[((size_t)xc * B_ * H_ * KL + bh * KL + k) * 8];
#pragma unroll
    for (int o = 0; o < 8; o++) orow[o] = bins[o];
}

// ---------------- K2c: reduce slices + argmax ----------------
__global__ void k2_argmax()
{
    int idx = blockIdx.x * blockDim.x + threadIdx.x;
    if (idx >= B_ * H_ * KL) return;
    float s[8];
#pragma unroll
    for (int o = 0; o < 8; o++) s[o] = 0.f;
    for (int xc = 0; xc < NSPLIT; xc++) {
        const float* p = &g_oriP[((size_t)xc * B_ * H_ * KL + idx) * 8];
#pragma unroll
        for (int o = 0; o < 8; o++) s[o] += p[o];
    }
    int best = 0;
    float bv = s[0];
#pragma unroll
    for (int p = 1; p < 8; p++)
        if (s[p] > bv) { bv = s[p]; best = p; }
    g_mo[idx] = best;
}

// ---------------- K3: kernel->x attention (f32x2, no-max softmax) ---------
__global__ __launch_bounds__(128) void k3_kattn(
    const float* __restrict__ dis_embed, const float* __restrict__ polar_emb)
{
    int k = threadIdx.x;
    int xs = blockIdx.x, h = blockIdx.y, b = blockIdx.z;
    int bh = b * H_ + h;
    __shared__ float kx_sh[64 * 32];
    __shared__ float V_sh[64 * 32];
    __shared__ unsigned pk_sh[128 * 33];
    __shared__ float de_sh[NDIS];
    __shared__ float pe_sh[8];
    if (k < NDIS) de_sh[k] = dis_embed[k * H_ + h];
    if (k < 8) pe_sh[k] = polar_emb[k];
    int mo = g_mo[bh * KL + k];

    uint64_t kq2[16];
    {
        const uint64_t* kqp = (const uint64_t*)&g_QKVk[((size_t)(b * KL + k)) * TDIM + h * HD];
#pragma unroll
        for (int i = 0; i < 16; i++) kq2[i] = kqp[i];
    }

    const unsigned* pkg = (const unsigned*)&g_pack[(size_t)bh * KL * XL];

    float l = 0.f;
    uint64_t acc2[16];
#pragma unroll
    for (int d = 0; d < 16; d++) acc2[d] = 0;

    int xbase = xs * (XL / NSPLIT);
    for (int c = 0; c < 2; c++) {
        int x0 = xbase + c * 64;
        __syncthreads();
        for (int g = threadIdx.x; g < 512; g += 128) {
            int row = g >> 3, c4 = g & 7;
            size_t rb = ((size_t)(b * XL + x0 + row)) * TDIM + h * HD + c4 * 4;
            ((float4*)kx_sh)[g] = *(const float4*)&g_QKVx[rb + DIM];
            ((float4*)V_sh)[g]  = *(const float4*)&g_QKVx[rb + 2 * DIM];
        }
        for (int g = threadIdx.x; g < 128 * 32; g += 128) {
            int row = g >> 5, col = g & 31;
            pk_sh[row * 33 + col] = pkg[(size_t)row * (XL / 2) + (x0 >> 1) + col];
        }
        __syncthreads();
        const unsigned short* prow = (const unsigned short*)&pk_sh[k * 33];
        for (int j0 = 0; j0 < 64; j0 += 4) {
#pragma unroll
            for (int jj = 0; jj < 4; jj++) {
                int j = j0 + jj;
                const ulonglong2* kx2 = (const ulonglong2*)&kx_sh[j * 32];
                uint64_t sa = 0;
#pragma unroll
                for (int d = 0; d < 8; d++) {
                    ulonglong2 v = kx2[d];
                    fma2(sa, kq2[2 * d], v.x);
                    fma2(sa, kq2[2 * d + 1], v.y);
                }
                float s0, s1;
                upk2(s0, s1, sa);
                unsigned short p = prow[j];
                float t = (s0 + s1) * SCALE + de_sh[p & 127] + pe_sh[(((p >> 7) & 7) - mo) & 7];
                float w = (p >> 10) ? 0.f : __expf(t);
                l += w;
                uint64_t wpk = pk2(w, w);
                const ulonglong2* vp = (const ulonglong2*)&V_sh[j * 32];
#pragma unroll
                for (int d = 0; d < 8; d++) {
                    ulonglong2 v = vp[d];
                    fma2(acc2[2 * d], wpk, v.x);
                    fma2(acc2[2 * d + 1], wpk, v.y);
                }
            }
        }
    }
    float* pp = &g_part[(((size_t)bh * NSPLIT + xs) * KL + k) * 33];
    pp[0] = l;
#pragma unroll
    for (int d = 0; d < 16; d++) {
        float a0, a1;
        upk2(a0, a1, acc2[d]);
        pp[1 + 2 * d] = a0;
        pp[2 + 2 * d] = a1;
    }
}

// ---------------- K3c: combine x-splits -> preK (bf16 hi/lo out) ----------
__global__ void k3_combine()
{
    int idx = blockIdx.x * blockDim.x + threadIdx.x;
    if (idx >= B_ * H_ * KL * 16) return;
    int d2 = idx & 15;
    int k = (idx >> 4) & (KL - 1);
    int bh = idx >> 11;
    int h = bh % H_, b = bh / H_;
    const float* base = &g_part[((size_t)bh * NSPLIT) * KL * 33 + (size_t)k * 33];
    float L = 0.f, A0 = 0.f, A1 = 0.f;
    const size_t SSTR = (size_t)KL * 33;
#pragma unroll 8
    for (int s = 0; s < NSPLIT; s++) {
        L  += base[s * SSTR];
        A0 += base[s * SSTR + 1 + 2 * d2];
        A1 += base[s * SSTR + 2 + 2 * d2];
    }
    float invL = 1.f / L;
    uint32_t lo, hi = split_pack(A0 * invL, A1 * invL, lo);
    size_t o = ((size_t)b * KL + k) * (DIM / 2) + h * (HD / 2) + d2;
    g_pKh[o] = hi;
    g_pKl[o] = lo;
}

// ---------------- K4: x->kernel attention (f32x2, bf16 hi/lo out) ---------
__global__ __launch_bounds__(128) void k4_xattn(
    const float* __restrict__ dis_embed, const float* __restrict__ polar_emb)
{
    __shared__ float kk_sh[KL * HD];
    __shared__ float kv_sh[KL * HD];
    __shared__ float de_sh[NDIS];
    __shared__ float pe_sh[8];
    __shared__ int   mo_sh[KL];
    int tid = threadIdx.x;
    int xc = blockIdx.x, h = blockIdx.y, b = blockIdx.z;
    int bh = b * H_ + h;

    for (int g = tid; g < KL * HD / 4; g += 128) {
        int row = g >> 3, c4 = g & 7;
        ((float4*)kk_sh)[g] =
            *(const float4*)&g_QKVk[((size_t)(b * KL + row)) * TDIM + DIM + h * HD + c4 * 4];
        ((float4*)kv_sh)[g] =
            *(const float4*)&g_QKVk[((size_t)(b * KL + row)) * TDIM + 2 * DIM + h * HD + c4 * 4];
    }
    if (tid < NDIS) de_sh[tid] = dis_embed[tid * H_ + h];
    if (tid < 8) pe_sh[tid] = polar_emb[tid];
    if (tid < KL) mo_sh[tid] = g_mo[bh * KL + tid];
    __syncthreads();

    int x = xc * 128 + tid;
    uint64_t q2[16];
    {
        const uint64_t* qp = (const uint64_t*)&g_QKVx[((size_t)(b * XL + x)) * TDIM + h * HD];
#pragma unroll
        for (int i = 0; i < 16; i++) q2[i] = qp[i];
    }
    const unsigned short* pk = &g_pack[(size_t)bh * KL * XL + x];

    float l = 0.f;
    uint64_t acc2[16];
#pragma unroll
    for (int d = 0; d < 16; d++) acc2[d] = 0;

    for (int k0 = 0; k0 < KL; k0 += 4) {
#pragma unroll
        for (int ki = 0; ki < 4; ki++) {
            int kidx = k0 + ki;
            const ulonglong2* kkp = (const ulonglong2*)&kk_sh[kidx * HD];
            uint64_t sa = 0;
#pragma unroll
            for (int d = 0; d < 8; d++) {
                ulonglong2 v = kkp[d];
                fma2(sa, q2[2 * d], v.x);
                fma2(sa, q2[2 * d + 1], v.y);
            }
            float s0, s1;
            upk2(s0, s1, sa);
            unsigned short p = pk[(size_t)kidx * XL];
            float t = (s0 + s1) * SCALE + de_sh[p & 127] + pe_sh[(((p >> 7) & 7) - mo_sh[kidx]) & 7];
            float w = (p >> 10) ? 0.f : __expf(t);
            l += w;
            uint64_t wpk = pk2(w, w);
            const ulonglong2* vp = (const ulonglong2*)&kv_sh[kidx * HD];
#pragma unroll
            for (int d = 0; d < 8; d++) {
                ulonglong2 v = vp[d];
                fma2(acc2[2 * d], wpk, v.x);
                fma2(acc2[2 * d + 1], wpk, v.y);
            }
        }
    }
    float invl = 1.f / l;
    size_t ob = ((size_t)(b * XL + x)) * (DIM / 2) + h * (HD / 2);
#pragma unroll
    for (int d2 = 0; d2 < 16; d2++) {
        float a0, a1;
        upk2(a0, a1, acc2[d2]);
        uint32_t lo, hi = split_pack(a0 * invl, a1 * invl, lo);
        g_pXh[ob + d2] = hi;
        g_pXl[ob + d2] = lo;
    }
}

// ---------------- host launcher ----------------
extern "C" void kernel_launch(void* const* d_in, const int* in_sizes, int n_in,
                              void* d_out, int out_size)
{
    const float* x     = (const float*)d_in[0];
    const float* kern  = (const float*)d_in[1];
    const int*   rd    = (const int*)d_in[2];
    const int*   polar = (const int*)d_in[3];
    const void*  mask  = d_in[4];
    const float* Wqkv  = (const float*)d_in[5];
    const float* dis   = (const float*)d_in[6];
    const float* pemb  = (const float*)d_in[7];
    const float* Wproj = (const float*)d_in[8];
    const float* bproj = (const float*)d_in[9];
    float* out = (float*)d_out;

    float* pQKVx; cudaGetSymbolAddress((void**)&pQKVx, g_QKVx);
    float* pQKVk; cudaGetSymbolAddress((void**)&pQKVk, g_QKVk);
    uint32_t *pxh, *pxl, *pkh, *pkl, *pwqh, *pwql, *pwph, *pwpl, *pXh, *pXl, *pKh, *pKl;
    cudaGetSymbolAddress((void**)&pxh, g_xhi);  cudaGetSymbolAddress((void**)&pxl, g_xlo);
    cudaGetSymbolAddress((void**)&pkh, g_khi);  cudaGetSymbolAddress((void**)&pkl, g_klo);
    cudaGetSymbolAddress((void**)&pwqh, g_wqh); cudaGetSymbolAddress((void**)&pwql, g_wql);
    cudaGetSymbolAddress((void**)&pwph, g_wph); cudaGetSymbolAddress((void**)&pwpl, g_wpl);
    cudaGetSymbolAddress((void**)&pXh, g_pXh);  cudaGetSymbolAddress((void**)&pXl, g_pXl);
    cudaGetSymbolAddress((void**)&pKh, g_pKh);  cudaGetSymbolAddress((void**)&pKl, g_pKl);

    // mask dtype probe + packed bias table
    det_reset<<<1, 32>>>();
    det_scan<<<256, 256>>>((const unsigned*)mask);
    pack16<<<dim3(XL / 64, KL / 32, B_), dim3(32, 8)>>>(mask, rd, polar);

    // pre-split GEMM operands
    presplitA<<<(B_ * XL * DIM / 2 + 255) / 256, 256>>>(x, pxh, pxl, B_ * XL * DIM / 2);
    presplitA<<<(B_ * KL * DIM / 2 + 255) / 256, 256>>>(kern, pkh, pkl, B_ * KL * DIM / 2);
    presplitB<<<((DIM / 2) * TDIM + 255) / 256, 256>>>(Wqkv, pwqh, pwql, TDIM, (DIM / 2) * TDIM);
    presplitB<<<((DIM / 2) * DIM + 255) / 256, 256>>>(Wproj, pwph, pwpl, DIM, (DIM / 2) * DIM);

    // QKV projections
    gemm_pre<<<dim3(TDIM / 128, (B_ * XL) / 128), 256>>>(pxh, pxl, pwqh, pwql, nullptr, pQKVx, B_ * XL, TDIM, DIM);
    gemm_pre<<<dim3(TDIM / 128, (B_ * KL) / 128), 256>>>(pkh, pkl, pwqh, pwql, nullptr, pQKVk, B_ * KL, TDIM, DIM);

    // orientation bins + argmax
    k2_scores<<<dim3(NSPLIT, H_, B_), 128>>>();
    k2_argmax<<<(B_ * H_ * KL + 255) / 256, 256>>>();

    // kernel->x attention
    k3_kattn<<<dim3(NSPLIT, H_, B_), 128>>>(dis, pemb);
    k3_combine<<<(B_ * H_ * KL * 16 + 255) / 256, 256>>>();

    // x->kernel attention
    k4_xattn<<<dim3(XL / 128, H_, B_), 128>>>(dis, pemb);

    // output projections
    gemm_pre<<<dim3(DIM / 128, (B_ * XL) / 128), 256>>>(pXh, pXl, pwph, pwpl, bproj, out, B_ * XL, DIM, DIM);
    gemm_pre<<<dim3(DIM / 128, (B_ * KL) / 128), 256>>>(pKh, pKl, pwph, pwpl, bproj, out + (size_t)B_ * XL * DIM, B_ * KL, DIM, DIM);
}